// round 2
// baseline (speedup 1.0000x reference)
#include <cuda_runtime.h>
#include <stdint.h>
#include <math.h>

#define N_NODES 8192
#define H_CH 256
#define HEADS 4
#define HEAD_DIM 64
#define E_EDGES 262144
#define WORDS_PER_ROW (N_NODES / 32)   // 256
#define CAP 2048                        // max tracked degree per row (mean is 32)

// ---------------- device scratch (no allocations allowed) ----------------
__device__ float    g_q[N_NODES * H_CH];
__device__ float    g_k[N_NODES * H_CH];
__device__ float    g_v[N_NODES * H_CH];
__device__ float    g_attn[N_NODES * H_CH];
__device__ unsigned g_bitmap[N_NODES * WORDS_PER_ROW];
__device__ int      g_is64;

// ---------------- edge dtype detection ----------------
// int64 values < 2^31: every odd 32-bit word (high half) is 0.
// int32 data: odd words are node indices in [0,8192) -- essentially never all 0.
__global__ void detect_dtype_kernel(const unsigned* __restrict__ ei_words) {
    if (threadIdx.x == 0 && blockIdx.x == 0) {
        int ok64 = 1;
        for (int i = 0; i < 128; i++) {
            if (ei_words[2 * i + 1] != 0u) { ok64 = 0; break; }
        }
        g_is64 = ok64;
    }
}

// ---------------- bitmap zero ----------------
__global__ void zero_bitmap_kernel() {
    int idx = blockIdx.x * blockDim.x + threadIdx.x;
    int total = N_NODES * WORDS_PER_ROW;
    for (int i = idx; i < total; i += gridDim.x * blockDim.x)
        g_bitmap[i] = 0u;
}

// ---------------- edge scatter (dedups via bitmap) ----------------
__global__ void scatter_edges_kernel(const void* __restrict__ ei_raw) {
    int e = blockIdx.x * blockDim.x + threadIdx.x;
    if (e >= E_EDGES) return;
    int r, c;
    if (g_is64) {
        const long long* ei = (const long long*)ei_raw;
        r = (int)ei[e];
        c = (int)ei[E_EDGES + e];
    } else {
        const int* ei = (const int*)ei_raw;
        r = ei[e];
        c = ei[E_EDGES + e];
    }
    if ((unsigned)r < N_NODES && (unsigned)c < N_NODES)
        atomicOr(&g_bitmap[r * WORDS_PER_ROW + (c >> 5)], 1u << (c & 31));
}

// ---------------- fp32 tiled GEMM: Y[M,N] = A[M,K] @ W[N,K]^T + bias ----------------
// 64x64 block tile, 256 threads, 4x4 register tile per thread, BK=16.
__global__ void gemm_bias_kernel(float* __restrict__ Y,
                                 const float* __restrict__ A,
                                 const float* __restrict__ W,
                                 const float* __restrict__ bias,
                                 int M, int N, int K) {
    __shared__ __align__(16) float As[16][68];
    __shared__ __align__(16) float Bs[16][68];

    int tid = threadIdx.x;
    int tx = tid & 15;
    int ty = tid >> 4;
    int rowBase = blockIdx.y * 64;
    int colBase = blockIdx.x * 64;

    int lr = tid >> 2;         // 0..63 : tile row loaded by this thread
    int lc = (tid & 3) * 4;    // 0,4,8,12 : k-offset

    float acc[4][4];
#pragma unroll
    for (int i = 0; i < 4; i++)
#pragma unroll
        for (int j = 0; j < 4; j++) acc[i][j] = 0.f;

    for (int kt = 0; kt < K; kt += 16) {
        float4 av = *(const float4*)&A[(size_t)(rowBase + lr) * K + kt + lc];
        float4 bv = *(const float4*)&W[(size_t)(colBase + lr) * K + kt + lc];
        As[lc + 0][lr] = av.x; As[lc + 1][lr] = av.y;
        As[lc + 2][lr] = av.z; As[lc + 3][lr] = av.w;
        Bs[lc + 0][lr] = bv.x; Bs[lc + 1][lr] = bv.y;
        Bs[lc + 2][lr] = bv.z; Bs[lc + 3][lr] = bv.w;
        __syncthreads();
#pragma unroll
        for (int kk = 0; kk < 16; kk++) {
            float4 a = *(const float4*)&As[kk][ty * 4];
            float4 b = *(const float4*)&Bs[kk][tx * 4];
            acc[0][0] += a.x * b.x; acc[0][1] += a.x * b.y; acc[0][2] += a.x * b.z; acc[0][3] += a.x * b.w;
            acc[1][0] += a.y * b.x; acc[1][1] += a.y * b.y; acc[1][2] += a.y * b.z; acc[1][3] += a.y * b.w;
            acc[2][0] += a.z * b.x; acc[2][1] += a.z * b.y; acc[2][2] += a.z * b.z; acc[2][3] += a.z * b.w;
            acc[3][0] += a.w * b.x; acc[3][1] += a.w * b.y; acc[3][2] += a.w * b.z; acc[3][3] += a.w * b.w;
        }
        __syncthreads();
    }

#pragma unroll
    for (int i = 0; i < 4; i++) {
        int row = rowBase + ty * 4 + i;
#pragma unroll
        for (int j = 0; j < 4; j++) {
            int col = colBase + tx * 4 + j;
            Y[(size_t)row * N + col] = acc[i][j] + bias[col];
        }
    }
}

// ---------------- sparse masked attention: one block per node ----------------
__global__ void attn_kernel(float* __restrict__ out,
                            const float* __restrict__ q,
                            const float* __restrict__ k,
                            const float* __restrict__ v) {
    __shared__ __align__(16) float q_s[H_CH];
    __shared__ unsigned short nbr[CAP];
    __shared__ float sc[HEADS][CAP];
    __shared__ int warpSum[8];
    __shared__ int warpBase[8];
    __shared__ int deg_s;
    __shared__ float linv_s[HEADS];

    int i = blockIdx.x;
    int tid = threadIdx.x;          // 256 threads
    int lane = tid & 31;
    int wid = tid >> 5;

    q_s[tid] = q[(size_t)i * H_CH + tid];

    // ---- deterministic neighbor gather via block prefix scan over bitmap words ----
    unsigned w = g_bitmap[i * WORDS_PER_ROW + tid];  // exactly one word per thread
    int c = __popc(w);
    int incl = c;
#pragma unroll
    for (int d = 1; d < 32; d <<= 1) {
        int n_ = __shfl_up_sync(0xffffffffu, incl, d);
        if (lane >= d) incl += n_;
    }
    if (lane == 31) warpSum[wid] = incl;
    __syncthreads();
    if (tid < 8) {
        int e = 0;
        for (int j2 = 0; j2 < tid; j2++) e += warpSum[j2];
        warpBase[tid] = e;
        if (tid == 7) deg_s = e + warpSum[7];
    }
    __syncthreads();
    int off = warpBase[wid] + (incl - c);
    unsigned ww = w;
    while (ww) {
        int b = __ffs(ww) - 1;
        ww &= ww - 1;
        if (off < CAP) nbr[off] = (unsigned short)(tid * 32 + b);
        off++;
    }
    __syncthreads();
    int deg = min(deg_s, CAP);

    // ---- scores: task = (neighbor j, head h), one thread per task ----
    for (int task = tid; task < deg * HEADS; task += 256) {
        int j = task >> 2;
        int h = task & 3;
        const float4* kp = (const float4*)(k + (size_t)nbr[j] * H_CH + h * HEAD_DIM);
        const float4* qp = (const float4*)(q_s + h * HEAD_DIM);
        float dot = 0.f;
#pragma unroll
        for (int t2 = 0; t2 < 16; t2++) {
            float4 kv = kp[t2];
            float4 qv = qp[t2];
            dot += kv.x * qv.x + kv.y * qv.y + kv.z * qv.z + kv.w * qv.w;
        }
        sc[h][j] = dot * 0.125f;  // 1/sqrt(64)
    }
    __syncthreads();

    // ---- per-head softmax (serial per head; deg ~ 32) ----
    if (tid < HEADS) {
        int h = tid;
        float m = -1e30f;
        for (int j = 0; j < deg; j++) m = fmaxf(m, sc[h][j]);
        float l = 0.f;
        for (int j = 0; j < deg; j++) {
            float p = __expf(sc[h][j] - m);
            sc[h][j] = p;
            l += p;
        }
        linv_s[h] = 1.0f / l;
    }
    __syncthreads();

    // ---- weighted V accumulation: thread t owns output channel t ----
    int h = tid >> 6;
    int d = tid & 63;
    float acc = 0.f;
    for (int j = 0; j < deg; j++)
        acc += sc[h][j] * v[(size_t)nbr[j] * H_CH + h * HEAD_DIM + d];
    out[(size_t)i * H_CH + tid] = acc * linv_s[h];
}

// ---------------- launch ----------------
extern "C" void kernel_launch(void* const* d_in, const int* in_sizes, int n_in,
                              void* d_out, int out_size) {
    const float* x  = (const float*)d_in[0];
    const void*  ei = d_in[1];
    const float* Wq = (const float*)d_in[2];
    const float* bq = (const float*)d_in[3];
    const float* Wk = (const float*)d_in[4];
    const float* bk = (const float*)d_in[5];
    const float* Wv = (const float*)d_in[6];
    const float* bv = (const float*)d_in[7];
    const float* Wo = (const float*)d_in[8];
    const float* bo = (const float*)d_in[9];
    float* out = (float*)d_out;

    float *qp, *kp, *vp, *ap;
    cudaGetSymbolAddress((void**)&qp, g_q);
    cudaGetSymbolAddress((void**)&kp, g_k);
    cudaGetSymbolAddress((void**)&vp, g_v);
    cudaGetSymbolAddress((void**)&ap, g_attn);

    // adjacency bitmap
    detect_dtype_kernel<<<1, 32>>>((const unsigned*)ei);
    zero_bitmap_kernel<<<512, 256>>>();
    scatter_edges_kernel<<<(E_EDGES + 255) / 256, 256>>>(ei);

    // projections
    dim3 ggrid(H_CH / 64, N_NODES / 64);
    gemm_bias_kernel<<<ggrid, 256>>>(qp, x, Wq, bq, N_NODES, H_CH, H_CH);
    gemm_bias_kernel<<<ggrid, 256>>>(kp, x, Wk, bk, N_NODES, H_CH, H_CH);
    gemm_bias_kernel<<<ggrid, 256>>>(vp, x, Wv, bv, N_NODES, H_CH, H_CH);

    // sparse masked attention
    attn_kernel<<<N_NODES, 256>>>(ap, qp, kp, vp);

    // output projection
    gemm_bias_kernel<<<ggrid, 256>>>(out, ap, Wo, bo, N_NODES, H_CH, H_CH);
}

// round 3
// speedup vs baseline: 1.4080x; 1.4080x over previous
#include <cuda_runtime.h>
#include <stdint.h>
#include <math.h>

#define N_NODES 8192
#define H_CH 256
#define HEADS 4
#define HEAD_DIM 64
#define E_EDGES 262144
#define WORDS_PER_ROW (N_NODES / 32)   // 256
#define CAP 2048

// ---------------- device scratch ----------------
__device__ __align__(128) float    g_q[N_NODES * H_CH];
__device__ __align__(128) float    g_k[N_NODES * H_CH];
__device__ __align__(128) float    g_v[N_NODES * H_CH];
__device__ __align__(128) float    g_attn[N_NODES * H_CH];
__device__ unsigned g_bitmap[N_NODES * WORDS_PER_ROW];
__device__ int      g_is64;

// ---------------- edge dtype detection (parallel) ----------------
__global__ void detect_dtype_kernel(const unsigned* __restrict__ ei_words) {
    __shared__ int bad[4];
    int tid = threadIdx.x;                 // 128 threads
    unsigned v = ei_words[2 * tid + 1];    // high half if int64
    unsigned b = __ballot_sync(0xffffffffu, v != 0u);
    if ((tid & 31) == 0) bad[tid >> 5] = (b != 0u);
    __syncthreads();
    if (tid == 0) g_is64 = !(bad[0] | bad[1] | bad[2] | bad[3]);
}

// ---------------- bitmap zero ----------------
__global__ void zero_bitmap_kernel() {
    int idx = blockIdx.x * blockDim.x + threadIdx.x;
    int total = N_NODES * WORDS_PER_ROW;
    for (int i = idx; i < total; i += gridDim.x * blockDim.x)
        g_bitmap[i] = 0u;
}

// ---------------- edge scatter ----------------
__global__ void scatter_edges_kernel(const void* __restrict__ ei_raw) {
    int e = blockIdx.x * blockDim.x + threadIdx.x;
    if (e >= E_EDGES) return;
    int r, c;
    if (g_is64) {
        const long long* ei = (const long long*)ei_raw;
        r = (int)ei[e];
        c = (int)ei[E_EDGES + e];
    } else {
        const int* ei = (const int*)ei_raw;
        r = ei[e];
        c = ei[E_EDGES + e];
    }
    if ((unsigned)r < N_NODES && (unsigned)c < N_NODES)
        atomicOr(&g_bitmap[r * WORDS_PER_ROW + (c >> 5)], 1u << (c & 31));
}

// ---------------- tf32 tensor-core GEMM: Y[M,N] = A[M,K] @ W[N,K]^T + bias ----
// Block tile M=128, N=64, K-chunk 32. 256 threads = 8 warps; warp w owns rows
// [16w,16w+16) x all 64 cols. mma.m16n8k8 tf32, ldmatrix feeds, stride-36 pad.
#define SM_STRIDE 36

__device__ __forceinline__ uint32_t f2tf32(float f) {
    uint32_t u;
    asm("cvt.rna.tf32.f32 %0, %1;" : "=r"(u) : "f"(f));
    return u;
}

__global__ __launch_bounds__(256) void gemm_tf32_kernel(
        float* __restrict__ Y,
        const float* __restrict__ A,
        const float* __restrict__ W,
        const float* __restrict__ bias) {
    const int M_K = 256;  // K == N == 256
    __shared__ __align__(16) uint32_t As[128 * SM_STRIDE];
    __shared__ __align__(16) uint32_t Bs[64 * SM_STRIDE];

    int tid = threadIdx.x;
    int lane = tid & 31;
    int warp = tid >> 5;
    int mBase = blockIdx.y * 128;
    int nBase = blockIdx.x * 64;

    float c[8][4];
#pragma unroll
    for (int i = 0; i < 8; i++)
#pragma unroll
        for (int j = 0; j < 4; j++) c[i][j] = 0.f;

    // ldmatrix per-lane address components
    int a_row = lane & 15;
    int a_col = (lane >> 4) << 2;              // 0 or 4
    int b_row = (lane & 7) | ((lane >> 1) & 8);
    int b_col = (lane >> 1) & 4;               // 0 or 4

    uint32_t as_base = (uint32_t)__cvta_generic_to_shared(As);
    uint32_t bs_base = (uint32_t)__cvta_generic_to_shared(Bs);
    uint32_t a_addr0 = as_base + ((warp * 16 + a_row) * SM_STRIDE + a_col) * 4u;

    int ld_row = tid >> 3;           // 0..31
    int ld_col = (tid & 7) * 4;      // 0..28

    for (int kt = 0; kt < M_K; kt += 32) {
        // A tile: 128 rows x 32 cols
#pragma unroll
        for (int p = 0; p < 4; p++) {
            int row = ld_row + p * 32;
            float4 v = *(const float4*)&A[(size_t)(mBase + row) * M_K + kt + ld_col];
            uint32_t* dst = &As[row * SM_STRIDE + ld_col];
            dst[0] = f2tf32(v.x); dst[1] = f2tf32(v.y);
            dst[2] = f2tf32(v.z); dst[3] = f2tf32(v.w);
        }
        // B tile: 64 rows x 32 cols
#pragma unroll
        for (int p = 0; p < 2; p++) {
            int row = ld_row + p * 32;
            float4 v = *(const float4*)&W[(size_t)(nBase + row) * M_K + kt + ld_col];
            uint32_t* dst = &Bs[row * SM_STRIDE + ld_col];
            dst[0] = f2tf32(v.x); dst[1] = f2tf32(v.y);
            dst[2] = f2tf32(v.z); dst[3] = f2tf32(v.w);
        }
        __syncthreads();

#pragma unroll
        for (int ks = 0; ks < 4; ks++) {
            int kc = ks * 8;
            uint32_t a0, a1, a2, a3;
            asm volatile(
                "ldmatrix.sync.aligned.m8n8.x4.shared.b16 {%0,%1,%2,%3}, [%4];"
                : "=r"(a0), "=r"(a1), "=r"(a2), "=r"(a3)
                : "r"(a_addr0 + kc * 4u));
#pragma unroll
            for (int g = 0; g < 4; g++) {
                uint32_t b0, b1, b2, b3;
                uint32_t baddr = bs_base +
                    ((g * 16 + b_row) * SM_STRIDE + kc + b_col) * 4u;
                asm volatile(
                    "ldmatrix.sync.aligned.m8n8.x4.shared.b16 {%0,%1,%2,%3}, [%4];"
                    : "=r"(b0), "=r"(b1), "=r"(b2), "=r"(b3)
                    : "r"(baddr));
                asm volatile(
                    "mma.sync.aligned.m16n8k8.row.col.f32.tf32.tf32.f32 "
                    "{%0,%1,%2,%3}, {%4,%5,%6,%7}, {%8,%9}, {%0,%1,%2,%3};"
                    : "+f"(c[2*g][0]), "+f"(c[2*g][1]), "+f"(c[2*g][2]), "+f"(c[2*g][3])
                    : "r"(a0), "r"(a1), "r"(a2), "r"(a3), "r"(b0), "r"(b1));
                asm volatile(
                    "mma.sync.aligned.m16n8k8.row.col.f32.tf32.tf32.f32 "
                    "{%0,%1,%2,%3}, {%4,%5,%6,%7}, {%8,%9}, {%0,%1,%2,%3};"
                    : "+f"(c[2*g+1][0]), "+f"(c[2*g+1][1]), "+f"(c[2*g+1][2]), "+f"(c[2*g+1][3])
                    : "r"(a0), "r"(a1), "r"(a2), "r"(a3), "r"(b2), "r"(b3));
            }
        }
        __syncthreads();
    }

    // epilogue: c0/c1 at (row, col), c2/c3 at (row+8, col); col = nf*8 + (lane%4)*2
    int row0 = mBase + warp * 16 + (lane >> 2);
#pragma unroll
    for (int nf = 0; nf < 8; nf++) {
        int col = nBase + nf * 8 + (lane & 3) * 2;
        float b0 = bias[col], b1 = bias[col + 1];
        *(float2*)&Y[(size_t)row0 * M_K + col] = make_float2(c[nf][0] + b0, c[nf][1] + b1);
        *(float2*)&Y[(size_t)(row0 + 8) * M_K + col] = make_float2(c[nf][2] + b0, c[nf][3] + b1);
    }
}

// ---------------- sparse masked attention: one block per node ----------------
__global__ void attn_kernel(float* __restrict__ out,
                            const float* __restrict__ q,
                            const float* __restrict__ k,
                            const float* __restrict__ v) {
    __shared__ __align__(16) float q_s[H_CH];
    __shared__ unsigned short nbr[CAP];
    __shared__ float sc[HEADS][CAP];
    __shared__ int warpSum[8];
    __shared__ int warpBase[8];
    __shared__ int deg_s;
    __shared__ float linv_s[HEADS];

    int i = blockIdx.x;
    int tid = threadIdx.x;
    int lane = tid & 31;
    int wid = tid >> 5;

    q_s[tid] = q[(size_t)i * H_CH + tid];

    unsigned w = g_bitmap[i * WORDS_PER_ROW + tid];
    int c = __popc(w);
    int incl = c;
#pragma unroll
    for (int d = 1; d < 32; d <<= 1) {
        int n_ = __shfl_up_sync(0xffffffffu, incl, d);
        if (lane >= d) incl += n_;
    }
    if (lane == 31) warpSum[wid] = incl;
    __syncthreads();
    if (tid < 8) {
        int e = 0;
        for (int j2 = 0; j2 < tid; j2++) e += warpSum[j2];
        warpBase[tid] = e;
        if (tid == 7) deg_s = e + warpSum[7];
    }
    __syncthreads();
    int off = warpBase[wid] + (incl - c);
    unsigned ww = w;
    while (ww) {
        int b = __ffs(ww) - 1;
        ww &= ww - 1;
        if (off < CAP) nbr[off] = (unsigned short)(tid * 32 + b);
        off++;
    }
    __syncthreads();
    int deg = min(deg_s, CAP);

    for (int task = tid; task < deg * HEADS; task += 256) {
        int j = task >> 2;
        int h = task & 3;
        const float4* kp = (const float4*)(k + (size_t)nbr[j] * H_CH + h * HEAD_DIM);
        const float4* qp = (const float4*)(q_s + h * HEAD_DIM);
        float dot = 0.f;
#pragma unroll
        for (int t2 = 0; t2 < 16; t2++) {
            float4 kv = kp[t2];
            float4 qv = qp[t2];
            dot += kv.x * qv.x + kv.y * qv.y + kv.z * qv.z + kv.w * qv.w;
        }
        sc[h][j] = dot * 0.125f;
    }
    __syncthreads();

    if (tid < HEADS) {
        int h = tid;
        float m = -1e30f;
        for (int j = 0; j < deg; j++) m = fmaxf(m, sc[h][j]);
        float l = 0.f;
        for (int j = 0; j < deg; j++) {
            float p = __expf(sc[h][j] - m);
            sc[h][j] = p;
            l += p;
        }
        linv_s[h] = 1.0f / l;
    }
    __syncthreads();

    int h = tid >> 6;
    int d = tid & 63;
    float acc = 0.f;
    for (int j = 0; j < deg; j++)
        acc += sc[h][j] * v[(size_t)nbr[j] * H_CH + h * HEAD_DIM + d];
    out[(size_t)i * H_CH + tid] = acc * linv_s[h];
}

// ---------------- launch ----------------
extern "C" void kernel_launch(void* const* d_in, const int* in_sizes, int n_in,
                              void* d_out, int out_size) {
    const float* x  = (const float*)d_in[0];
    const void*  ei = d_in[1];
    const float* Wq = (const float*)d_in[2];
    const float* bq = (const float*)d_in[3];
    const float* Wk = (const float*)d_in[4];
    const float* bk = (const float*)d_in[5];
    const float* Wv = (const float*)d_in[6];
    const float* bv = (const float*)d_in[7];
    const float* Wo = (const float*)d_in[8];
    const float* bo = (const float*)d_in[9];
    float* out = (float*)d_out;

    float *qp, *kp, *vp, *ap;
    cudaGetSymbolAddress((void**)&qp, g_q);
    cudaGetSymbolAddress((void**)&kp, g_k);
    cudaGetSymbolAddress((void**)&vp, g_v);
    cudaGetSymbolAddress((void**)&ap, g_attn);

    detect_dtype_kernel<<<1, 128>>>((const unsigned*)ei);
    zero_bitmap_kernel<<<512, 256>>>();
    scatter_edges_kernel<<<(E_EDGES + 255) / 256, 256>>>(ei);

    dim3 ggrid(H_CH / 64, N_NODES / 128);
    gemm_tf32_kernel<<<ggrid, 256>>>(qp, x, Wq, bq);
    gemm_tf32_kernel<<<ggrid, 256>>>(kp, x, Wk, bk);
    gemm_tf32_kernel<<<ggrid, 256>>>(vp, x, Wv, bv);

    attn_kernel<<<N_NODES, 256>>>(ap, qp, kp, vp);

    gemm_tf32_kernel<<<ggrid, 256>>>(out, ap, Wo, bo);
}

// round 5
// speedup vs baseline: 1.5532x; 1.1031x over previous
#include <cuda_runtime.h>
#include <stdint.h>
#include <math.h>

#define N_NODES 8192
#define H_CH 256
#define HEADS 4
#define HEAD_DIM 64
#define E_EDGES 262144
#define WORDS_PER_ROW (N_NODES / 32)   // 256
#define CAP 256                         // Poisson(32) max deg ~65; 256 is ~30 sigma

// ---------------- device scratch ----------------
__device__ __align__(128) float    g_q[N_NODES * H_CH];
__device__ __align__(128) float    g_k[N_NODES * H_CH];
__device__ __align__(128) float    g_v[N_NODES * H_CH];
__device__ __align__(128) float    g_attn[N_NODES * H_CH];
__device__ unsigned g_bitmap[N_NODES * WORDS_PER_ROW];
__device__ int      g_is64;

// ---------------- edge dtype detection (parallel) ----------------
__global__ void detect_dtype_kernel(const unsigned* __restrict__ ei_words) {
    __shared__ int bad[4];
    int tid = threadIdx.x;                 // 128 threads
    unsigned v = ei_words[2 * tid + 1];    // high half if int64
    unsigned b = __ballot_sync(0xffffffffu, v != 0u);
    if ((tid & 31) == 0) bad[tid >> 5] = (b != 0u);
    __syncthreads();
    if (tid == 0) g_is64 = !(bad[0] | bad[1] | bad[2] | bad[3]);
}

// ---------------- bitmap zero ----------------
__global__ void zero_bitmap_kernel() {
    int idx = blockIdx.x * blockDim.x + threadIdx.x;
    int total = N_NODES * WORDS_PER_ROW;
    for (int i = idx; i < total; i += gridDim.x * blockDim.x)
        g_bitmap[i] = 0u;
}

// ---------------- edge scatter ----------------
__global__ void scatter_edges_kernel(const void* __restrict__ ei_raw) {
    int e = blockIdx.x * blockDim.x + threadIdx.x;
    if (e >= E_EDGES) return;
    int r, c;
    if (g_is64) {
        const long long* ei = (const long long*)ei_raw;
        r = (int)ei[e];
        c = (int)ei[E_EDGES + e];
    } else {
        const int* ei = (const int*)ei_raw;
        r = ei[e];
        c = ei[E_EDGES + e];
    }
    if ((unsigned)r < N_NODES && (unsigned)c < N_NODES)
        atomicOr(&g_bitmap[r * WORDS_PER_ROW + (c >> 5)], 1u << (c & 31));
}

// ---------------- tf32 tensor-core GEMM: Y[M,256] = A[M,256] @ W[256,256]^T + b ----
// Block tile M=128, N=64, K-chunk 32; 8 warps; register-prefetch pipeline.
// blockIdx.z selects one of up to 3 (Y, W, bias) problems sharing A.
#define SM_STRIDE 36

__device__ __forceinline__ uint32_t f2tf32(float f) {
    uint32_t u;
    asm("cvt.rna.tf32.f32 %0, %1;" : "=r"(u) : "f"(f));
    return u;
}

__global__ __launch_bounds__(256) void gemm_tf32_kernel(
        float* __restrict__ Y0, float* __restrict__ Y1, float* __restrict__ Y2,
        const float* __restrict__ A,
        const float* __restrict__ W0, const float* __restrict__ W1, const float* __restrict__ W2,
        const float* __restrict__ b0p, const float* __restrict__ b1p, const float* __restrict__ b2p) {
    const int M_K = 256;
    __shared__ __align__(16) uint32_t As[128 * SM_STRIDE];
    __shared__ __align__(16) uint32_t Bs[64 * SM_STRIDE];

    int z = blockIdx.z;
    float* Y = (z == 0) ? Y0 : (z == 1) ? Y1 : Y2;
    const float* W = (z == 0) ? W0 : (z == 1) ? W1 : W2;
    const float* bias = (z == 0) ? b0p : (z == 1) ? b1p : b2p;

    int tid = threadIdx.x;
    int lane = tid & 31;
    int warp = tid >> 5;
    int mBase = blockIdx.y * 128;
    int nBase = blockIdx.x * 64;

    float c[8][4];
#pragma unroll
    for (int i = 0; i < 8; i++)
#pragma unroll
        for (int j = 0; j < 4; j++) c[i][j] = 0.f;

    int a_row = lane & 15;
    int a_col = (lane >> 4) << 2;
    int b_row = (lane & 7) | ((lane >> 1) & 8);
    int b_col = (lane >> 1) & 4;

    uint32_t as_base = (uint32_t)__cvta_generic_to_shared(As);
    uint32_t bs_base = (uint32_t)__cvta_generic_to_shared(Bs);
    uint32_t a_addr0 = as_base + ((warp * 16 + a_row) * SM_STRIDE + a_col) * 4u;

    int ld_row = tid >> 3;           // 0..31
    int ld_col = (tid & 7) * 4;      // 0..28

    const float* aSrc = &A[(size_t)(mBase + ld_row) * M_K + ld_col];
    const float* bSrc = &W[(size_t)(nBase + ld_row) * M_K + ld_col];

    float4 aReg[4], bReg[2];
    // prologue: chunk 0
#pragma unroll
    for (int p = 0; p < 4; p++) aReg[p] = *(const float4*)(aSrc + (size_t)p * 32 * M_K);
#pragma unroll
    for (int p = 0; p < 2; p++) bReg[p] = *(const float4*)(bSrc + (size_t)p * 32 * M_K);

    for (int kt = 0; kt < 8; kt++) {
        // stage current chunk to smem (cvt to tf32)
#pragma unroll
        for (int p = 0; p < 4; p++) {
            uint32_t* dst = &As[(ld_row + p * 32) * SM_STRIDE + ld_col];
            dst[0] = f2tf32(aReg[p].x); dst[1] = f2tf32(aReg[p].y);
            dst[2] = f2tf32(aReg[p].z); dst[3] = f2tf32(aReg[p].w);
        }
#pragma unroll
        for (int p = 0; p < 2; p++) {
            uint32_t* dst = &Bs[(ld_row + p * 32) * SM_STRIDE + ld_col];
            dst[0] = f2tf32(bReg[p].x); dst[1] = f2tf32(bReg[p].y);
            dst[2] = f2tf32(bReg[p].z); dst[3] = f2tf32(bReg[p].w);
        }
        __syncthreads();

        // prefetch next chunk while mma runs
        if (kt < 7) {
            int koff = (kt + 1) * 32;
#pragma unroll
            for (int p = 0; p < 4; p++) aReg[p] = *(const float4*)(aSrc + (size_t)p * 32 * M_K + koff);
#pragma unroll
            for (int p = 0; p < 2; p++) bReg[p] = *(const float4*)(bSrc + (size_t)p * 32 * M_K + koff);
        }

#pragma unroll
        for (int ks = 0; ks < 4; ks++) {
            int kc = ks * 8;
            uint32_t a0, a1, a2, a3;
            asm volatile(
                "ldmatrix.sync.aligned.m8n8.x4.shared.b16 {%0,%1,%2,%3}, [%4];"
                : "=r"(a0), "=r"(a1), "=r"(a2), "=r"(a3)
                : "r"(a_addr0 + kc * 4u));
#pragma unroll
            for (int g = 0; g < 4; g++) {
                uint32_t b0, b1, b2, b3;
                uint32_t baddr = bs_base +
                    ((g * 16 + b_row) * SM_STRIDE + kc + b_col) * 4u;
                asm volatile(
                    "ldmatrix.sync.aligned.m8n8.x4.shared.b16 {%0,%1,%2,%3}, [%4];"
                    : "=r"(b0), "=r"(b1), "=r"(b2), "=r"(b3)
                    : "r"(baddr));
                asm volatile(
                    "mma.sync.aligned.m16n8k8.row.col.f32.tf32.tf32.f32 "
                    "{%0,%1,%2,%3}, {%4,%5,%6,%7}, {%8,%9}, {%0,%1,%2,%3};"
                    : "+f"(c[2*g][0]), "+f"(c[2*g][1]), "+f"(c[2*g][2]), "+f"(c[2*g][3])
                    : "r"(a0), "r"(a1), "r"(a2), "r"(a3), "r"(b0), "r"(b1));
                asm volatile(
                    "mma.sync.aligned.m16n8k8.row.col.f32.tf32.tf32.f32 "
                    "{%0,%1,%2,%3}, {%4,%5,%6,%7}, {%8,%9}, {%0,%1,%2,%3};"
                    : "+f"(c[2*g+1][0]), "+f"(c[2*g+1][1]), "+f"(c[2*g+1][2]), "+f"(c[2*g+1][3])
                    : "r"(a0), "r"(a1), "r"(a2), "r"(a3), "r"(b2), "r"(b3));
            }
        }
        __syncthreads();
    }

    int row0 = mBase + warp * 16 + (lane >> 2);
#pragma unroll
    for (int nf = 0; nf < 8; nf++) {
        int col = nBase + nf * 8 + (lane & 3) * 2;
        float b0 = bias[col], b1 = bias[col + 1];
        *(float2*)&Y[(size_t)row0 * M_K + col] = make_float2(c[nf][0] + b0, c[nf][1] + b1);
        *(float2*)&Y[(size_t)(row0 + 8) * M_K + col] = make_float2(c[nf][2] + b0, c[nf][3] + b1);
    }
}

// ---------------- sparse masked attention: one block per node ----------------
__global__ __launch_bounds__(256) void attn_kernel(
        float* __restrict__ out,
        const float* __restrict__ q,
        const float* __restrict__ k,
        const float* __restrict__ v) {
    __shared__ __align__(16) float q_s[H_CH];
    __shared__ unsigned short nbr[CAP];
    __shared__ float sc[HEADS][CAP];
    __shared__ int warpSum[8];
    __shared__ int warpBase[8];
    __shared__ int deg_s;
    __shared__ float linv_s[HEADS];

    int i = blockIdx.x;
    int tid = threadIdx.x;
    int lane = tid & 31;
    int wid = tid >> 5;

    q_s[tid] = q[(size_t)i * H_CH + tid];

    // deterministic neighbor gather: block prefix scan over bitmap words
    unsigned w = g_bitmap[i * WORDS_PER_ROW + tid];
    int c = __popc(w);
    int incl = c;
#pragma unroll
    for (int d = 1; d < 32; d <<= 1) {
        int n_ = __shfl_up_sync(0xffffffffu, incl, d);
        if (lane >= d) incl += n_;
    }
    if (lane == 31) warpSum[wid] = incl;
    __syncthreads();
    if (tid < 8) {
        int e = 0;
        for (int j2 = 0; j2 < tid; j2++) e += warpSum[j2];
        warpBase[tid] = e;
        if (tid == 7) deg_s = e + warpSum[7];
    }
    __syncthreads();
    int off = warpBase[wid] + (incl - c);
    unsigned ww = w;
    while (ww) {
        int b = __ffs(ww) - 1;
        ww &= ww - 1;
        if (off < CAP) nbr[off] = (unsigned short)(tid * 32 + b);
        off++;
    }
    __syncthreads();
    int deg = min(deg_s, CAP);

    // scores: task = (neighbor j, head h)
    for (int task = tid; task < deg * HEADS; task += 256) {
        int j = task >> 2;
        int h = task & 3;
        const float4* kp = (const float4*)(k + (size_t)nbr[j] * H_CH + h * HEAD_DIM);
        const float4* qp = (const float4*)(q_s + h * HEAD_DIM);
        float dot = 0.f;
#pragma unroll
        for (int t2 = 0; t2 < 16; t2++) {
            float4 kv = kp[t2];
            float4 qv = qp[t2];
            dot += kv.x * qv.x + kv.y * qv.y + kv.z * qv.z + kv.w * qv.w;
        }
        sc[h][j] = dot * 0.125f;
    }
    __syncthreads();

    // per-head softmax: warp h handles head h (lane-strided + shuffle reduce)
    if (wid < HEADS) {
        int h = wid;
        float m = -1e30f;
        for (int j = lane; j < deg; j += 32) m = fmaxf(m, sc[h][j]);
#pragma unroll
        for (int d = 16; d; d >>= 1) m = fmaxf(m, __shfl_xor_sync(0xffffffffu, m, d));
        float l = 0.f;
        for (int j = lane; j < deg; j += 32) {
            float p = __expf(sc[h][j] - m);
            sc[h][j] = p;
            l += p;
        }
#pragma unroll
        for (int d = 16; d; d >>= 1) l += __shfl_xor_sync(0xffffffffu, l, d);
        if (lane == 0) linv_s[h] = 1.0f / l;
    }
    __syncthreads();

    // weighted V accumulation: thread t owns output channel t (coalesced v reads)
    int h = tid >> 6;
    int d = tid & 63;
    float acc = 0.f;
    for (int j = 0; j < deg; j++)
        acc += sc[h][j] * v[(size_t)nbr[j] * H_CH + h * HEAD_DIM + d];
    out[(size_t)i * H_CH + tid] = acc * linv_s[h];
}

// ---------------- launch ----------------
extern "C" void kernel_launch(void* const* d_in, const int* in_sizes, int n_in,
                              void* d_out, int out_size) {
    const float* x  = (const float*)d_in[0];
    const void*  ei = d_in[1];
    const float* Wq = (const float*)d_in[2];
    const float* bq = (const float*)d_in[3];
    const float* Wk = (const float*)d_in[4];
    const float* bk = (const float*)d_in[5];
    const float* Wv = (const float*)d_in[6];
    const float* bv = (const float*)d_in[7];
    const float* Wo = (const float*)d_in[8];
    const float* bo = (const float*)d_in[9];
    float* out = (float*)d_out;

    float *qp, *kp, *vp, *ap;
    cudaGetSymbolAddress((void**)&qp, g_q);
    cudaGetSymbolAddress((void**)&kp, g_k);
    cudaGetSymbolAddress((void**)&vp, g_v);
    cudaGetSymbolAddress((void**)&ap, g_attn);

    detect_dtype_kernel<<<1, 128>>>((const unsigned*)ei);
    zero_bitmap_kernel<<<512, 256>>>();
    scatter_edges_kernel<<<(E_EDGES + 255) / 256, 256>>>(ei);

    // fused Q/K/V projections: blockIdx.z selects problem
    dim3 qkv_grid(H_CH / 64, N_NODES / 128, 3);
    gemm_tf32_kernel<<<qkv_grid, 256>>>(qp, kp, vp, x, Wq, Wk, Wv, bq, bk, bv);

    attn_kernel<<<N_NODES, 256>>>(ap, qp, kp, vp);

    // output projection (single problem)
    dim3 o_grid(H_CH / 64, N_NODES / 128, 1);
    gemm_tf32_kernel<<<o_grid, 256>>>(out, out, out, ap, Wo, Wo, Wo, bo, bo, bo);
}

// round 6
// speedup vs baseline: 1.9344x; 1.2454x over previous
#include <cuda_runtime.h>
#include <stdint.h>
#include <math.h>

#define N_NODES 8192
#define H_CH 256
#define HEADS 4
#define HEAD_DIM 64
#define E_EDGES 262144
#define WORDS_PER_ROW (N_NODES / 32)   // 256
#define CAP 256

// ---------------- device scratch ----------------
__device__ __align__(128) float    g_q[N_NODES * H_CH];
__device__ __align__(128) float    g_k[N_NODES * H_CH];
__device__ __align__(128) float    g_v[N_NODES * H_CH];
__device__ __align__(128) float    g_attn[N_NODES * H_CH];
__device__ unsigned g_bitmap[N_NODES * WORDS_PER_ROW];
__device__ int      g_is64;

// ---------------- edge dtype detection (parallel) ----------------
__global__ void detect_dtype_kernel(const unsigned* __restrict__ ei_words) {
    __shared__ int bad[4];
    int tid = threadIdx.x;                 // 128 threads
    unsigned v = ei_words[2 * tid + 1];    // high half if int64
    unsigned b = __ballot_sync(0xffffffffu, v != 0u);
    if ((tid & 31) == 0) bad[tid >> 5] = (b != 0u);
    __syncthreads();
    if (tid == 0) g_is64 = !(bad[0] | bad[1] | bad[2] | bad[3]);
}

// ---------------- bitmap zero ----------------
__global__ void zero_bitmap_kernel() {
    int idx = blockIdx.x * blockDim.x + threadIdx.x;
    int total = N_NODES * WORDS_PER_ROW;
    for (int i = idx; i < total; i += gridDim.x * blockDim.x)
        g_bitmap[i] = 0u;
}

// ---------------- edge scatter ----------------
__global__ void scatter_edges_kernel(const void* __restrict__ ei_raw) {
    int e = blockIdx.x * blockDim.x + threadIdx.x;
    if (e >= E_EDGES) return;
    int r, c;
    if (g_is64) {
        const long long* ei = (const long long*)ei_raw;
        r = (int)ei[e];
        c = (int)ei[E_EDGES + e];
    } else {
        const int* ei = (const int*)ei_raw;
        r = ei[e];
        c = ei[E_EDGES + e];
    }
    if ((unsigned)r < N_NODES && (unsigned)c < N_NODES)
        atomicOr(&g_bitmap[r * WORDS_PER_ROW + (c >> 5)], 1u << (c & 31));
}

// ---------------- tf32 tensor-core GEMM: Y[M,256] = A[M,256] @ W[256,256]^T + b ----
#define SM_STRIDE 36

__device__ __forceinline__ uint32_t f2tf32(float f) {
    uint32_t u;
    asm("cvt.rna.tf32.f32 %0, %1;" : "=r"(u) : "f"(f));
    return u;
}

__global__ __launch_bounds__(256) void gemm_tf32_kernel(
        float* __restrict__ Y0, float* __restrict__ Y1, float* __restrict__ Y2,
        const float* __restrict__ A,
        const float* __restrict__ W0, const float* __restrict__ W1, const float* __restrict__ W2,
        const float* __restrict__ b0p, const float* __restrict__ b1p, const float* __restrict__ b2p) {
    const int M_K = 256;
    __shared__ __align__(16) uint32_t As[128 * SM_STRIDE];
    __shared__ __align__(16) uint32_t Bs[64 * SM_STRIDE];

    int z = blockIdx.z;
    float* Y = (z == 0) ? Y0 : (z == 1) ? Y1 : Y2;
    const float* W = (z == 0) ? W0 : (z == 1) ? W1 : W2;
    const float* bias = (z == 0) ? b0p : (z == 1) ? b1p : b2p;

    int tid = threadIdx.x;
    int lane = tid & 31;
    int warp = tid >> 5;
    int mBase = blockIdx.y * 128;
    int nBase = blockIdx.x * 64;

    float c[8][4];
#pragma unroll
    for (int i = 0; i < 8; i++)
#pragma unroll
        for (int j = 0; j < 4; j++) c[i][j] = 0.f;

    int a_row = lane & 15;
    int a_col = (lane >> 4) << 2;
    int b_row = (lane & 7) | ((lane >> 1) & 8);
    int b_col = (lane >> 1) & 4;

    uint32_t as_base = (uint32_t)__cvta_generic_to_shared(As);
    uint32_t bs_base = (uint32_t)__cvta_generic_to_shared(Bs);
    uint32_t a_addr0 = as_base + ((warp * 16 + a_row) * SM_STRIDE + a_col) * 4u;

    int ld_row = tid >> 3;           // 0..31
    int ld_col = (tid & 7) * 4;      // 0..28

    const float* aSrc = &A[(size_t)(mBase + ld_row) * M_K + ld_col];
    const float* bSrc = &W[(size_t)(nBase + ld_row) * M_K + ld_col];

    float4 aReg[4], bReg[2];
#pragma unroll
    for (int p = 0; p < 4; p++) aReg[p] = *(const float4*)(aSrc + (size_t)p * 32 * M_K);
#pragma unroll
    for (int p = 0; p < 2; p++) bReg[p] = *(const float4*)(bSrc + (size_t)p * 32 * M_K);

    for (int kt = 0; kt < 8; kt++) {
#pragma unroll
        for (int p = 0; p < 4; p++) {
            uint32_t* dst = &As[(ld_row + p * 32) * SM_STRIDE + ld_col];
            dst[0] = f2tf32(aReg[p].x); dst[1] = f2tf32(aReg[p].y);
            dst[2] = f2tf32(aReg[p].z); dst[3] = f2tf32(aReg[p].w);
        }
#pragma unroll
        for (int p = 0; p < 2; p++) {
            uint32_t* dst = &Bs[(ld_row + p * 32) * SM_STRIDE + ld_col];
            dst[0] = f2tf32(bReg[p].x); dst[1] = f2tf32(bReg[p].y);
            dst[2] = f2tf32(bReg[p].z); dst[3] = f2tf32(bReg[p].w);
        }
        __syncthreads();

        if (kt < 7) {
            int koff = (kt + 1) * 32;
#pragma unroll
            for (int p = 0; p < 4; p++) aReg[p] = *(const float4*)(aSrc + (size_t)p * 32 * M_K + koff);
#pragma unroll
            for (int p = 0; p < 2; p++) bReg[p] = *(const float4*)(bSrc + (size_t)p * 32 * M_K + koff);
        }

#pragma unroll
        for (int ks = 0; ks < 4; ks++) {
            int kc = ks * 8;
            uint32_t a0, a1, a2, a3;
            asm volatile(
                "ldmatrix.sync.aligned.m8n8.x4.shared.b16 {%0,%1,%2,%3}, [%4];"
                : "=r"(a0), "=r"(a1), "=r"(a2), "=r"(a3)
                : "r"(a_addr0 + kc * 4u));
#pragma unroll
            for (int g = 0; g < 4; g++) {
                uint32_t b0, b1, b2, b3;
                uint32_t baddr = bs_base +
                    ((g * 16 + b_row) * SM_STRIDE + kc + b_col) * 4u;
                asm volatile(
                    "ldmatrix.sync.aligned.m8n8.x4.shared.b16 {%0,%1,%2,%3}, [%4];"
                    : "=r"(b0), "=r"(b1), "=r"(b2), "=r"(b3)
                    : "r"(baddr));
                asm volatile(
                    "mma.sync.aligned.m16n8k8.row.col.f32.tf32.tf32.f32 "
                    "{%0,%1,%2,%3}, {%4,%5,%6,%7}, {%8,%9}, {%0,%1,%2,%3};"
                    : "+f"(c[2*g][0]), "+f"(c[2*g][1]), "+f"(c[2*g][2]), "+f"(c[2*g][3])
                    : "r"(a0), "r"(a1), "r"(a2), "r"(a3), "r"(b0), "r"(b1));
                asm volatile(
                    "mma.sync.aligned.m16n8k8.row.col.f32.tf32.tf32.f32 "
                    "{%0,%1,%2,%3}, {%4,%5,%6,%7}, {%8,%9}, {%0,%1,%2,%3};"
                    : "+f"(c[2*g+1][0]), "+f"(c[2*g+1][1]), "+f"(c[2*g+1][2]), "+f"(c[2*g+1][3])
                    : "r"(a0), "r"(a1), "r"(a2), "r"(a3), "r"(b2), "r"(b3));
            }
        }
        __syncthreads();
    }

    int row0 = mBase + warp * 16 + (lane >> 2);
#pragma unroll
    for (int nf = 0; nf < 8; nf++) {
        int col = nBase + nf * 8 + (lane & 3) * 2;
        float b0 = bias[col], b1 = bias[col + 1];
        *(float2*)&Y[(size_t)row0 * M_K + col] = make_float2(c[nf][0] + b0, c[nf][1] + b1);
        *(float2*)&Y[(size_t)(row0 + 8) * M_K + col] = make_float2(c[nf][2] + b0, c[nf][3] + b1);
    }
}

// ---------------- sparse masked attention: 128-thread block per node ----------------
__global__ __launch_bounds__(128) void attn_kernel(
        float* __restrict__ out,
        const float* __restrict__ q,
        const float* __restrict__ k,
        const float* __restrict__ v) {
    __shared__ __align__(16) float q_s[H_CH];
    __shared__ unsigned short nbr[CAP];
    __shared__ float sc[HEADS][CAP];
    __shared__ int warpSum[4];
    __shared__ int warpBase[4];
    __shared__ int deg_s;
    __shared__ float linv_s[HEADS];

    int i = blockIdx.x;
    int tid = threadIdx.x;          // 128 threads
    int lane = tid & 31;
    int wid = tid >> 5;             // 0..3

    // q row: 128 threads x 2 floats
    *(float2*)&q_s[tid * 2] = *(const float2*)&q[(size_t)i * H_CH + tid * 2];

    // ---- deterministic neighbor gather: each thread owns 2 consecutive words ----
    uint2 wpair = *(const uint2*)&g_bitmap[i * WORDS_PER_ROW + tid * 2];
    unsigned w0 = wpair.x, w1 = wpair.y;
    int c = __popc(w0) + __popc(w1);
    int incl = c;
#pragma unroll
    for (int d = 1; d < 32; d <<= 1) {
        int n_ = __shfl_up_sync(0xffffffffu, incl, d);
        if (lane >= d) incl += n_;
    }
    if (lane == 31) warpSum[wid] = incl;
    __syncthreads();
    if (tid < 4) {
        int e = 0;
        for (int j2 = 0; j2 < tid; j2++) e += warpSum[j2];
        warpBase[tid] = e;
        if (tid == 3) deg_s = e + warpSum[3];
    }
    __syncthreads();
    int off = warpBase[wid] + (incl - c);
    int base0 = tid * 64;
    while (w0) {
        int b = __ffs(w0) - 1;
        w0 &= w0 - 1;
        if (off < CAP) nbr[off] = (unsigned short)(base0 + b);
        off++;
    }
    while (w1) {
        int b = __ffs(w1) - 1;
        w1 &= w1 - 1;
        if (off < CAP) nbr[off] = (unsigned short)(base0 + 32 + b);
        off++;
    }
    __syncthreads();
    int deg = min(deg_s, CAP);

    // ---- scores: task = (neighbor j, head h); deg*4 tasks on 128 threads ----
    for (int task = tid; task < deg * HEADS; task += 128) {
        int j = task >> 2;
        int h = task & 3;
        const float4* kp = (const float4*)(k + (size_t)nbr[j] * H_CH + h * HEAD_DIM);
        const float4* qp = (const float4*)(q_s + h * HEAD_DIM);
        float dot = 0.f;
#pragma unroll
        for (int t2 = 0; t2 < 16; t2++) {
            float4 kv = kp[t2];
            float4 qv = qp[t2];
            dot += kv.x * qv.x + kv.y * qv.y + kv.z * qv.z + kv.w * qv.w;
        }
        sc[h][j] = dot * 0.125f;
    }
    __syncthreads();

    // ---- per-head softmax: warp h handles head h ----
    {
        int h = wid;
        float m = -1e30f;
        for (int j = lane; j < deg; j += 32) m = fmaxf(m, sc[h][j]);
#pragma unroll
        for (int d = 16; d; d >>= 1) m = fmaxf(m, __shfl_xor_sync(0xffffffffu, m, d));
        float l = 0.f;
        for (int j = lane; j < deg; j += 32) {
            float p = __expf(sc[h][j] - m);
            sc[h][j] = p;
            l += p;
        }
#pragma unroll
        for (int d = 16; d; d >>= 1) l += __shfl_xor_sync(0xffffffffu, l, d);
        if (lane == 0) linv_s[h] = 1.0f / l;
    }
    __syncthreads();

    // ---- weighted V: thread t owns channels t and t+128; unroll x4 (8 loads in flight) ----
    int h0 = tid >> 6;          // 0 or 1
    int h1 = h0 + 2;            // 2 or 3
    int ch0 = tid;
    int ch1 = tid + 128;
    float acc0 = 0.f, acc1 = 0.f;
    int j = 0;
    for (; j + 3 < deg; j += 4) {
        int n0 = nbr[j], n1 = nbr[j + 1], n2 = nbr[j + 2], n3 = nbr[j + 3];
        float s00 = sc[h0][j],     s01 = sc[h0][j + 1], s02 = sc[h0][j + 2], s03 = sc[h0][j + 3];
        float s10 = sc[h1][j],     s11 = sc[h1][j + 1], s12 = sc[h1][j + 2], s13 = sc[h1][j + 3];
        float v00 = v[(size_t)n0 * H_CH + ch0];
        float v01 = v[(size_t)n1 * H_CH + ch0];
        float v02 = v[(size_t)n2 * H_CH + ch0];
        float v03 = v[(size_t)n3 * H_CH + ch0];
        float v10 = v[(size_t)n0 * H_CH + ch1];
        float v11 = v[(size_t)n1 * H_CH + ch1];
        float v12 = v[(size_t)n2 * H_CH + ch1];
        float v13 = v[(size_t)n3 * H_CH + ch1];
        acc0 += s00 * v00 + s01 * v01 + s02 * v02 + s03 * v03;
        acc1 += s10 * v10 + s11 * v11 + s12 * v12 + s13 * v13;
    }
    for (; j < deg; j++) {
        int n = nbr[j];
        acc0 += sc[h0][j] * v[(size_t)n * H_CH + ch0];
        acc1 += sc[h1][j] * v[(size_t)n * H_CH + ch1];
    }
    out[(size_t)i * H_CH + ch0] = acc0 * linv_s[h0];
    out[(size_t)i * H_CH + ch1] = acc1 * linv_s[h1];
}

// ---------------- launch ----------------
extern "C" void kernel_launch(void* const* d_in, const int* in_sizes, int n_in,
                              void* d_out, int out_size) {
    const float* x  = (const float*)d_in[0];
    const void*  ei = d_in[1];
    const float* Wq = (const float*)d_in[2];
    const float* bq = (const float*)d_in[3];
    const float* Wk = (const float*)d_in[4];
    const float* bk = (const float*)d_in[5];
    const float* Wv = (const float*)d_in[6];
    const float* bv = (const float*)d_in[7];
    const float* Wo = (const float*)d_in[8];
    const float* bo = (const float*)d_in[9];
    float* out = (float*)d_out;

    float *qp, *kp, *vp, *ap;
    cudaGetSymbolAddress((void**)&qp, g_q);
    cudaGetSymbolAddress((void**)&kp, g_k);
    cudaGetSymbolAddress((void**)&vp, g_v);
    cudaGetSymbolAddress((void**)&ap, g_attn);

    detect_dtype_kernel<<<1, 128>>>((const unsigned*)ei);
    zero_bitmap_kernel<<<512, 256>>>();
    scatter_edges_kernel<<<(E_EDGES + 255) / 256, 256>>>(ei);

    dim3 qkv_grid(H_CH / 64, N_NODES / 128, 3);
    gemm_tf32_kernel<<<qkv_grid, 256>>>(qp, kp, vp, x, Wq, Wk, Wv, bq, bk, bv);

    attn_kernel<<<N_NODES, 128>>>(ap, qp, kp, vp);

    dim3 o_grid(H_CH / 64, N_NODES / 128, 1);
    gemm_tf32_kernel<<<o_grid, 256>>>(out, out, out, ap, Wo, Wo, Wo, bo, bo, bo);
}

// round 7
// speedup vs baseline: 2.9333x; 1.5164x over previous
#include <cuda_runtime.h>
#include <stdint.h>
#include <math.h>

#define N_NODES 8192
#define H_CH 256
#define HEADS 4
#define HEAD_DIM 64
#define E_EDGES 262144
#define WORDS_PER_ROW (N_NODES / 32)   // 256
#define CAP 256

// ---------------- device scratch ----------------
__device__ __align__(128) float    g_q[N_NODES * H_CH];
__device__ __align__(128) float    g_k[N_NODES * H_CH];
__device__ __align__(128) float    g_v[N_NODES * H_CH];
__device__ __align__(128) float    g_attn[N_NODES * H_CH];
__device__ unsigned g_bitmap[N_NODES * WORDS_PER_ROW];
__device__ int      g_is64;

// ---------------- edge dtype detection (parallel) ----------------
__global__ void detect_dtype_kernel(const unsigned* __restrict__ ei_words) {
    __shared__ int bad[4];
    int tid = threadIdx.x;                 // 128 threads
    unsigned v = ei_words[2 * tid + 1];    // high half if int64
    unsigned b = __ballot_sync(0xffffffffu, v != 0u);
    if ((tid & 31) == 0) bad[tid >> 5] = (b != 0u);
    __syncthreads();
    if (tid == 0) g_is64 = !(bad[0] | bad[1] | bad[2] | bad[3]);
}

// ---------------- bitmap zero ----------------
__global__ void zero_bitmap_kernel() {
    int idx = blockIdx.x * blockDim.x + threadIdx.x;
    int total = N_NODES * WORDS_PER_ROW;
    for (int i = idx; i < total; i += gridDim.x * blockDim.x)
        g_bitmap[i] = 0u;
}

// ---------------- edge scatter ----------------
__global__ void scatter_edges_kernel(const void* __restrict__ ei_raw) {
    int e = blockIdx.x * blockDim.x + threadIdx.x;
    if (e >= E_EDGES) return;
    int r, c;
    if (g_is64) {
        const long long* ei = (const long long*)ei_raw;
        r = (int)ei[e];
        c = (int)ei[E_EDGES + e];
    } else {
        const int* ei = (const int*)ei_raw;
        r = ei[e];
        c = ei[E_EDGES + e];
    }
    if ((unsigned)r < N_NODES && (unsigned)c < N_NODES)
        atomicOr(&g_bitmap[r * WORDS_PER_ROW + (c >> 5)], 1u << (c & 31));
}

// ---------------- tf32 tensor-core GEMM: Y[M,256] = A[M,256] @ W[256,256]^T + b ----
#define SM_STRIDE 36

__device__ __forceinline__ uint32_t f2tf32(float f) {
    uint32_t u;
    asm("cvt.rna.tf32.f32 %0, %1;" : "=r"(u) : "f"(f));
    return u;
}

__global__ __launch_bounds__(256) void gemm_tf32_kernel(
        float* __restrict__ Y0, float* __restrict__ Y1, float* __restrict__ Y2,
        const float* __restrict__ A,
        const float* __restrict__ W0, const float* __restrict__ W1, const float* __restrict__ W2,
        const float* __restrict__ b0p, const float* __restrict__ b1p, const float* __restrict__ b2p) {
    const int M_K = 256;
    __shared__ __align__(16) uint32_t As[128 * SM_STRIDE];
    __shared__ __align__(16) uint32_t Bs[64 * SM_STRIDE];

    int z = blockIdx.z;
    float* Y = (z == 0) ? Y0 : (z == 1) ? Y1 : Y2;
    const float* W = (z == 0) ? W0 : (z == 1) ? W1 : W2;
    const float* bias = (z == 0) ? b0p : (z == 1) ? b1p : b2p;

    int tid = threadIdx.x;
    int lane = tid & 31;
    int warp = tid >> 5;
    int mBase = blockIdx.y * 128;
    int nBase = blockIdx.x * 64;

    float c[8][4];
#pragma unroll
    for (int i = 0; i < 8; i++)
#pragma unroll
        for (int j = 0; j < 4; j++) c[i][j] = 0.f;

    int a_row = lane & 15;
    int a_col = (lane >> 4) << 2;
    int b_row = (lane & 7) | ((lane >> 1) & 8);
    int b_col = (lane >> 1) & 4;

    uint32_t as_base = (uint32_t)__cvta_generic_to_shared(As);
    uint32_t bs_base = (uint32_t)__cvta_generic_to_shared(Bs);
    uint32_t a_addr0 = as_base + ((warp * 16 + a_row) * SM_STRIDE + a_col) * 4u;

    int ld_row = tid >> 3;           // 0..31
    int ld_col = (tid & 7) * 4;      // 0..28

    const float* aSrc = &A[(size_t)(mBase + ld_row) * M_K + ld_col];
    const float* bSrc = &W[(size_t)(nBase + ld_row) * M_K + ld_col];

    float4 aReg[4], bReg[2];
#pragma unroll
    for (int p = 0; p < 4; p++) aReg[p] = *(const float4*)(aSrc + (size_t)p * 32 * M_K);
#pragma unroll
    for (int p = 0; p < 2; p++) bReg[p] = *(const float4*)(bSrc + (size_t)p * 32 * M_K);

    for (int kt = 0; kt < 8; kt++) {
#pragma unroll
        for (int p = 0; p < 4; p++) {
            uint32_t* dst = &As[(ld_row + p * 32) * SM_STRIDE + ld_col];
            dst[0] = f2tf32(aReg[p].x); dst[1] = f2tf32(aReg[p].y);
            dst[2] = f2tf32(aReg[p].z); dst[3] = f2tf32(aReg[p].w);
        }
#pragma unroll
        for (int p = 0; p < 2; p++) {
            uint32_t* dst = &Bs[(ld_row + p * 32) * SM_STRIDE + ld_col];
            dst[0] = f2tf32(bReg[p].x); dst[1] = f2tf32(bReg[p].y);
            dst[2] = f2tf32(bReg[p].z); dst[3] = f2tf32(bReg[p].w);
        }
        __syncthreads();

        if (kt < 7) {
            int koff = (kt + 1) * 32;
#pragma unroll
            for (int p = 0; p < 4; p++) aReg[p] = *(const float4*)(aSrc + (size_t)p * 32 * M_K + koff);
#pragma unroll
            for (int p = 0; p < 2; p++) bReg[p] = *(const float4*)(bSrc + (size_t)p * 32 * M_K + koff);
        }

#pragma unroll
        for (int ks = 0; ks < 4; ks++) {
            int kc = ks * 8;
            uint32_t a0, a1, a2, a3;
            asm volatile(
                "ldmatrix.sync.aligned.m8n8.x4.shared.b16 {%0,%1,%2,%3}, [%4];"
                : "=r"(a0), "=r"(a1), "=r"(a2), "=r"(a3)
                : "r"(a_addr0 + kc * 4u));
#pragma unroll
            for (int g = 0; g < 4; g++) {
                uint32_t b0, b1, b2, b3;
                uint32_t baddr = bs_base +
                    ((g * 16 + b_row) * SM_STRIDE + kc + b_col) * 4u;
                asm volatile(
                    "ldmatrix.sync.aligned.m8n8.x4.shared.b16 {%0,%1,%2,%3}, [%4];"
                    : "=r"(b0), "=r"(b1), "=r"(b2), "=r"(b3)
                    : "r"(baddr));
                asm volatile(
                    "mma.sync.aligned.m16n8k8.row.col.f32.tf32.tf32.f32 "
                    "{%0,%1,%2,%3}, {%4,%5,%6,%7}, {%8,%9}, {%0,%1,%2,%3};"
                    : "+f"(c[2*g][0]), "+f"(c[2*g][1]), "+f"(c[2*g][2]), "+f"(c[2*g][3])
                    : "r"(a0), "r"(a1), "r"(a2), "r"(a3), "r"(b0), "r"(b1));
                asm volatile(
                    "mma.sync.aligned.m16n8k8.row.col.f32.tf32.tf32.f32 "
                    "{%0,%1,%2,%3}, {%4,%5,%6,%7}, {%8,%9}, {%0,%1,%2,%3};"
                    : "+f"(c[2*g+1][0]), "+f"(c[2*g+1][1]), "+f"(c[2*g+1][2]), "+f"(c[2*g+1][3])
                    : "r"(a0), "r"(a1), "r"(a2), "r"(a3), "r"(b2), "r"(b3));
            }
        }
        __syncthreads();
    }

    int row0 = mBase + warp * 16 + (lane >> 2);
#pragma unroll
    for (int nf = 0; nf < 8; nf++) {
        int col = nBase + nf * 8 + (lane & 3) * 2;
        float b0 = bias[col], b1 = bias[col + 1];
        *(float2*)&Y[(size_t)row0 * M_K + col] = make_float2(c[nf][0] + b0, c[nf][1] + b1);
        *(float2*)&Y[(size_t)(row0 + 8) * M_K + col] = make_float2(c[nf][2] + b0, c[nf][3] + b1);
    }
}

// ---------------- sparse masked attention: warp w = head w, all loads coalesced ----
__global__ __launch_bounds__(128) void attn_kernel(
        float* __restrict__ out,
        const float* __restrict__ q,
        const float* __restrict__ k,
        const float* __restrict__ v) {
    __shared__ unsigned short nbr[CAP];
    __shared__ float sc[HEADS][CAP];
    __shared__ int warpSum[4];
    __shared__ int warpBase[4];
    __shared__ int deg_s;

    int i = blockIdx.x;
    int tid = threadIdx.x;          // 128 threads
    int lane = tid & 31;
    int wid = tid >> 5;             // = head index

    // ---- deterministic neighbor gather: each thread owns 2 consecutive words ----
    uint2 wpair = *(const uint2*)&g_bitmap[i * WORDS_PER_ROW + tid * 2];
    unsigned w0 = wpair.x, w1 = wpair.y;
    int c = __popc(w0) + __popc(w1);
    int incl = c;
#pragma unroll
    for (int d = 1; d < 32; d <<= 1) {
        int n_ = __shfl_up_sync(0xffffffffu, incl, d);
        if (lane >= d) incl += n_;
    }
    if (lane == 31) warpSum[wid] = incl;
    __syncthreads();
    if (tid < 4) {
        int e = 0;
        for (int j2 = 0; j2 < tid; j2++) e += warpSum[j2];
        warpBase[tid] = e;
        if (tid == 3) deg_s = e + warpSum[3];
    }
    __syncthreads();
    int off = warpBase[wid] + (incl - c);
    int base0 = tid * 64;
    while (w0) {
        int b = __ffs(w0) - 1;
        w0 &= w0 - 1;
        if (off < CAP) nbr[off] = (unsigned short)(base0 + b);
        off++;
    }
    while (w1) {
        int b = __ffs(w1) - 1;
        w1 &= w1 - 1;
        if (off < CAP) nbr[off] = (unsigned short)(base0 + 32 + b);
        off++;
    }
    __syncthreads();
    int deg = min(deg_s, CAP);

    // warp wid owns head wid; lane owns channels {2*lane, 2*lane+1} of that head
    size_t headOff = (size_t)wid * HEAD_DIM + 2 * lane;
    float2 qv = *(const float2*)(q + (size_t)i * H_CH + headOff);

    // ---- scores: per neighbor, coalesced 256B K-row load + butterfly reduce ----
    int j = 0;
    for (; j + 1 < deg; j += 2) {
        int n0 = nbr[j], n1 = nbr[j + 1];
        float2 k0 = *(const float2*)(k + (size_t)n0 * H_CH + headOff);
        float2 k1 = *(const float2*)(k + (size_t)n1 * H_CH + headOff);
        float p0 = k0.x * qv.x + k0.y * qv.y;
        float p1 = k1.x * qv.x + k1.y * qv.y;
#pragma unroll
        for (int d = 16; d; d >>= 1) {
            p0 += __shfl_xor_sync(0xffffffffu, p0, d);
            p1 += __shfl_xor_sync(0xffffffffu, p1, d);
        }
        if (lane == 0) {
            sc[wid][j]     = p0 * 0.125f;
            sc[wid][j + 1] = p1 * 0.125f;
        }
    }
    if (j < deg) {
        int n0 = nbr[j];
        float2 k0 = *(const float2*)(k + (size_t)n0 * H_CH + headOff);
        float p0 = k0.x * qv.x + k0.y * qv.y;
#pragma unroll
        for (int d = 16; d; d >>= 1) p0 += __shfl_xor_sync(0xffffffffu, p0, d);
        if (lane == 0) sc[wid][j] = p0 * 0.125f;
    }
    __syncwarp();

    // ---- warp-local softmax over sc[wid][0..deg) ----
    float m = -1e30f;
    for (int t = lane; t < deg; t += 32) m = fmaxf(m, sc[wid][t]);
#pragma unroll
    for (int d = 16; d; d >>= 1) m = fmaxf(m, __shfl_xor_sync(0xffffffffu, m, d));
    float l = 0.f;
    for (int t = lane; t < deg; t += 32) {
        float p = __expf(sc[wid][t] - m);
        sc[wid][t] = p;
        l += p;
    }
#pragma unroll
    for (int d = 16; d; d >>= 1) l += __shfl_xor_sync(0xffffffffu, l, d);
    float linv = 1.0f / l;
    __syncwarp();

    // ---- weighted V: coalesced 256B V-row loads ----
    float accx = 0.f, accy = 0.f;
    int t = 0;
    for (; t + 3 < deg; t += 4) {
        int n0 = nbr[t], n1 = nbr[t + 1], n2 = nbr[t + 2], n3 = nbr[t + 3];
        float s0 = sc[wid][t], s1 = sc[wid][t + 1], s2 = sc[wid][t + 2], s3 = sc[wid][t + 3];
        float2 v0 = *(const float2*)(v + (size_t)n0 * H_CH + headOff);
        float2 v1 = *(const float2*)(v + (size_t)n1 * H_CH + headOff);
        float2 v2 = *(const float2*)(v + (size_t)n2 * H_CH + headOff);
        float2 v3 = *(const float2*)(v + (size_t)n3 * H_CH + headOff);
        accx += s0 * v0.x + s1 * v1.x + s2 * v2.x + s3 * v3.x;
        accy += s0 * v0.y + s1 * v1.y + s2 * v2.y + s3 * v3.y;
    }
    for (; t < deg; t++) {
        int n = nbr[t];
        float s = sc[wid][t];
        float2 vv = *(const float2*)(v + (size_t)n * H_CH + headOff);
        accx += s * vv.x;
        accy += s * vv.y;
    }
    *(float2*)(out + (size_t)i * H_CH + headOff) = make_float2(accx * linv, accy * linv);
}

// ---------------- launch ----------------
extern "C" void kernel_launch(void* const* d_in, const int* in_sizes, int n_in,
                              void* d_out, int out_size) {
    const float* x  = (const float*)d_in[0];
    const void*  ei = d_in[1];
    const float* Wq = (const float*)d_in[2];
    const float* bq = (const float*)d_in[3];
    const float* Wk = (const float*)d_in[4];
    const float* bk = (const float*)d_in[5];
    const float* Wv = (const float*)d_in[6];
    const float* bv = (const float*)d_in[7];
    const float* Wo = (const float*)d_in[8];
    const float* bo = (const float*)d_in[9];
    float* out = (float*)d_out;

    float *qp, *kp, *vp, *ap;
    cudaGetSymbolAddress((void**)&qp, g_q);
    cudaGetSymbolAddress((void**)&kp, g_k);
    cudaGetSymbolAddress((void**)&vp, g_v);
    cudaGetSymbolAddress((void**)&ap, g_attn);

    detect_dtype_kernel<<<1, 128>>>((const unsigned*)ei);
    zero_bitmap_kernel<<<512, 256>>>();
    scatter_edges_kernel<<<(E_EDGES + 255) / 256, 256>>>(ei);

    dim3 qkv_grid(H_CH / 64, N_NODES / 128, 3);
    gemm_tf32_kernel<<<qkv_grid, 256>>>(qp, kp, vp, x, Wq, Wk, Wv, bq, bk, bv);

    attn_kernel<<<N_NODES, 128>>>(ap, qp, kp, vp);

    dim3 o_grid(H_CH / 64, N_NODES / 128, 1);
    gemm_tf32_kernel<<<o_grid, 256>>>(out, out, out, ap, Wo, Wo, Wo, bo, bo, bo);
}

// round 9
// speedup vs baseline: 3.3795x; 1.1521x over previous
#include <cuda_runtime.h>
#include <stdint.h>
#include <math.h>

#define N_NODES 8192
#define H_CH 256
#define HEADS 4
#define HEAD_DIM 64
#define E_EDGES 262144
#define WORDS_PER_ROW (N_NODES / 32)   // 256
#define CAP 256

// ---------------- device scratch ----------------
__device__ __align__(128) float    g_q[N_NODES * H_CH];
__device__ __align__(128) float    g_k[N_NODES * H_CH];
__device__ __align__(128) float    g_v[N_NODES * H_CH];
__device__ __align__(128) float    g_attn[N_NODES * H_CH];
__device__ unsigned g_bitmap[N_NODES * WORDS_PER_ROW];
__device__ int      g_is64;

// ---------------- edge dtype detection (parallel) ----------------
__global__ void detect_dtype_kernel(const unsigned* __restrict__ ei_words) {
    __shared__ int bad[4];
    int tid = threadIdx.x;                 // 128 threads
    unsigned v = ei_words[2 * tid + 1];    // high half if int64
    unsigned b = __ballot_sync(0xffffffffu, v != 0u);
    if ((tid & 31) == 0) bad[tid >> 5] = (b != 0u);
    __syncthreads();
    if (tid == 0) g_is64 = !(bad[0] | bad[1] | bad[2] | bad[3]);
}

// ---------------- bitmap zero ----------------
__global__ void zero_bitmap_kernel() {
    int idx = blockIdx.x * blockDim.x + threadIdx.x;
    int total = N_NODES * WORDS_PER_ROW;
    for (int i = idx; i < total; i += gridDim.x * blockDim.x)
        g_bitmap[i] = 0u;
}

// ---------------- edge scatter ----------------
__global__ void scatter_edges_kernel(const void* __restrict__ ei_raw) {
    int e = blockIdx.x * blockDim.x + threadIdx.x;
    if (e >= E_EDGES) return;
    int r, c;
    if (g_is64) {
        const long long* ei = (const long long*)ei_raw;
        r = (int)ei[e];
        c = (int)ei[E_EDGES + e];
    } else {
        const int* ei = (const int*)ei_raw;
        r = ei[e];
        c = ei[E_EDGES + e];
    }
    if ((unsigned)r < N_NODES && (unsigned)c < N_NODES)
        atomicOr(&g_bitmap[r * WORDS_PER_ROW + (c >> 5)], 1u << (c & 31));
}

// ---------------- tf32 tensor-core GEMM (double-buffered dynamic smem) ----------
#define SM_STRIDE 36
#define A_WORDS (128 * SM_STRIDE)
#define B_WORDS (64 * SM_STRIDE)
#define GEMM_SMEM_BYTES (2 * (A_WORDS + B_WORDS) * 4)   // 55296

__device__ __forceinline__ uint32_t f2tf32(float f) {
    uint32_t u;
    asm("cvt.rna.tf32.f32 %0, %1;" : "=r"(u) : "f"(f));
    return u;
}

__global__ __launch_bounds__(256) void gemm_tf32_kernel(
        float* __restrict__ Y0, float* __restrict__ Y1, float* __restrict__ Y2,
        const float* __restrict__ A,
        const float* __restrict__ W0, const float* __restrict__ W1, const float* __restrict__ W2,
        const float* __restrict__ b0p, const float* __restrict__ b1p, const float* __restrict__ b2p) {
    const int M_K = 256;
    extern __shared__ __align__(16) uint32_t smem[];
    // layout: As[0] As[1] Bs[0] Bs[1]
    uint32_t* AsBuf[2] = { smem, smem + A_WORDS };
    uint32_t* BsBuf[2] = { smem + 2 * A_WORDS, smem + 2 * A_WORDS + B_WORDS };

    int z = blockIdx.z;
    float* Y = (z == 0) ? Y0 : (z == 1) ? Y1 : Y2;
    const float* W = (z == 0) ? W0 : (z == 1) ? W1 : W2;
    const float* bias = (z == 0) ? b0p : (z == 1) ? b1p : b2p;

    int tid = threadIdx.x;
    int lane = tid & 31;
    int warp = tid >> 5;
    int mBase = blockIdx.y * 128;
    int nBase = blockIdx.x * 64;

    float c[8][4];
#pragma unroll
    for (int i = 0; i < 8; i++)
#pragma unroll
        for (int j = 0; j < 4; j++) c[i][j] = 0.f;

    int a_row = lane & 15;
    int a_col = (lane >> 4) << 2;
    int b_row = (lane & 7) | ((lane >> 1) & 8);
    int b_col = (lane >> 1) & 4;

    uint32_t as_base = (uint32_t)__cvta_generic_to_shared(smem);
    uint32_t bs_base = as_base + 2u * A_WORDS * 4u;
    uint32_t a_addr0 = as_base + ((warp * 16 + a_row) * SM_STRIDE + a_col) * 4u;

    int ld_row = tid >> 3;           // 0..31
    int ld_col = (tid & 7) * 4;      // 0..28

    const float* aSrc = &A[(size_t)(mBase + ld_row) * M_K + ld_col];
    const float* bSrc = &W[(size_t)(nBase + ld_row) * M_K + ld_col];

    float4 aReg[4], bReg[2];
#pragma unroll
    for (int p = 0; p < 4; p++) aReg[p] = *(const float4*)(aSrc + (size_t)p * 32 * M_K);
#pragma unroll
    for (int p = 0; p < 2; p++) bReg[p] = *(const float4*)(bSrc + (size_t)p * 32 * M_K);

    for (int kt = 0; kt < 8; kt++) {
        int buf = kt & 1;
#pragma unroll
        for (int p = 0; p < 4; p++) {
            uint32_t* dst = &AsBuf[buf][(ld_row + p * 32) * SM_STRIDE + ld_col];
            dst[0] = f2tf32(aReg[p].x); dst[1] = f2tf32(aReg[p].y);
            dst[2] = f2tf32(aReg[p].z); dst[3] = f2tf32(aReg[p].w);
        }
#pragma unroll
        for (int p = 0; p < 2; p++) {
            uint32_t* dst = &BsBuf[buf][(ld_row + p * 32) * SM_STRIDE + ld_col];
            dst[0] = f2tf32(bReg[p].x); dst[1] = f2tf32(bReg[p].y);
            dst[2] = f2tf32(bReg[p].z); dst[3] = f2tf32(bReg[p].w);
        }
        __syncthreads();   // single barrier per iter (double buffer removes WAR hazard)

        if (kt < 7) {
            int koff = (kt + 1) * 32;
#pragma unroll
            for (int p = 0; p < 4; p++) aReg[p] = *(const float4*)(aSrc + (size_t)p * 32 * M_K + koff);
#pragma unroll
            for (int p = 0; p < 2; p++) bReg[p] = *(const float4*)(bSrc + (size_t)p * 32 * M_K + koff);
        }

        uint32_t aBufOff = (uint32_t)buf * (A_WORDS * 4u);
        uint32_t bBufOff = (uint32_t)buf * (B_WORDS * 4u);
#pragma unroll
        for (int ks = 0; ks < 4; ks++) {
            int kc = ks * 8;
            uint32_t a0, a1, a2, a3;
            asm volatile(
                "ldmatrix.sync.aligned.m8n8.x4.shared.b16 {%0,%1,%2,%3}, [%4];"
                : "=r"(a0), "=r"(a1), "=r"(a2), "=r"(a3)
                : "r"(a_addr0 + aBufOff + kc * 4u));
#pragma unroll
            for (int g = 0; g < 4; g++) {
                uint32_t b0, b1, b2, b3;
                uint32_t baddr = bs_base + bBufOff +
                    ((g * 16 + b_row) * SM_STRIDE + kc + b_col) * 4u;
                asm volatile(
                    "ldmatrix.sync.aligned.m8n8.x4.shared.b16 {%0,%1,%2,%3}, [%4];"
                    : "=r"(b0), "=r"(b1), "=r"(b2), "=r"(b3)
                    : "r"(baddr));
                asm volatile(
                    "mma.sync.aligned.m16n8k8.row.col.f32.tf32.tf32.f32 "
                    "{%0,%1,%2,%3}, {%4,%5,%6,%7}, {%8,%9}, {%0,%1,%2,%3};"
                    : "+f"(c[2*g][0]), "+f"(c[2*g][1]), "+f"(c[2*g][2]), "+f"(c[2*g][3])
                    : "r"(a0), "r"(a1), "r"(a2), "r"(a3), "r"(b0), "r"(b1));
                asm volatile(
                    "mma.sync.aligned.m16n8k8.row.col.f32.tf32.tf32.f32 "
                    "{%0,%1,%2,%3}, {%4,%5,%6,%7}, {%8,%9}, {%0,%1,%2,%3};"
                    : "+f"(c[2*g+1][0]), "+f"(c[2*g+1][1]), "+f"(c[2*g+1][2]), "+f"(c[2*g+1][3])
                    : "r"(a0), "r"(a1), "r"(a2), "r"(a3), "r"(b2), "r"(b3));
            }
        }
    }

    int row0 = mBase + warp * 16 + (lane >> 2);
#pragma unroll
    for (int nf = 0; nf < 8; nf++) {
        int col = nBase + nf * 8 + (lane & 3) * 2;
        float b0 = bias[col], b1 = bias[col + 1];
        *(float2*)&Y[(size_t)row0 * M_K + col] = make_float2(c[nf][0] + b0, c[nf][1] + b1);
        *(float2*)&Y[(size_t)(row0 + 8) * M_K + col] = make_float2(c[nf][2] + b0, c[nf][3] + b1);
    }
}

// ---------------- sparse masked attention: warp w = head w ----------------
__global__ __launch_bounds__(128) void attn_kernel(
        float* __restrict__ out,
        const float* __restrict__ q,
        const float* __restrict__ k,
        const float* __restrict__ v) {
    __shared__ unsigned short nbr[CAP];
    __shared__ float sc[HEADS][CAP];
    __shared__ int warpSum[4];
    __shared__ int warpBase[4];
    __shared__ int deg_s;

    int i = blockIdx.x;
    int tid = threadIdx.x;          // 128 threads
    int lane = tid & 31;
    int wid = tid >> 5;             // = head index

    // ---- deterministic neighbor gather ----
    uint2 wpair = *(const uint2*)&g_bitmap[i * WORDS_PER_ROW + tid * 2];
    unsigned w0 = wpair.x, w1 = wpair.y;
    int c = __popc(w0) + __popc(w1);
    int incl = c;
#pragma unroll
    for (int d = 1; d < 32; d <<= 1) {
        int n_ = __shfl_up_sync(0xffffffffu, incl, d);
        if (lane >= d) incl += n_;
    }
    if (lane == 31) warpSum[wid] = incl;
    __syncthreads();
    if (tid < 4) {
        int e = 0;
        for (int j2 = 0; j2 < tid; j2++) e += warpSum[j2];
        warpBase[tid] = e;
        if (tid == 3) deg_s = e + warpSum[3];
    }
    __syncthreads();
    int off = warpBase[wid] + (incl - c);
    int base0 = tid * 64;
    while (w0) {
        int b = __ffs(w0) - 1;
        w0 &= w0 - 1;
        if (off < CAP) nbr[off] = (unsigned short)(base0 + b);
        off++;
    }
    while (w1) {
        int b = __ffs(w1) - 1;
        w1 &= w1 - 1;
        if (off < CAP) nbr[off] = (unsigned short)(base0 + 32 + b);
        off++;
    }
    __syncthreads();
    int deg = min(deg_s, CAP);

    // ---- scores: 4 neighbors per warp-iter; 8-lane groups, 3-level reduce ----
    {
        int sub = lane >> 3;
        int chBase = (lane & 7) * 8;
        const float* qRow = q + (size_t)i * H_CH + wid * HEAD_DIM + chBase;
        float4 q0 = *(const float4*)qRow;
        float4 q1 = *(const float4*)(qRow + 4);
        for (int j = 0; j < deg; j += 4) {
            int jj = j + sub;
            bool valid = (jj < deg);
            int n = nbr[valid ? jj : 0];
            const float* kRow = k + (size_t)n * H_CH + wid * HEAD_DIM + chBase;
            float4 k0 = *(const float4*)kRow;
            float4 k1 = *(const float4*)(kRow + 4);
            float p = k0.x * q0.x + k0.y * q0.y + k0.z * q0.z + k0.w * q0.w
                    + k1.x * q1.x + k1.y * q1.y + k1.z * q1.z + k1.w * q1.w;
            p += __shfl_xor_sync(0xffffffffu, p, 1);
            p += __shfl_xor_sync(0xffffffffu, p, 2);
            p += __shfl_xor_sync(0xffffffffu, p, 4);
            if (valid && (lane & 7) == 0) sc[wid][jj] = p * 0.125f;
        }
    }
    __syncwarp();

    // ---- warp-local softmax over sc[wid][0..deg) ----
    float m = -1e30f;
    for (int t = lane; t < deg; t += 32) m = fmaxf(m, sc[wid][t]);
#pragma unroll
    for (int d = 16; d; d >>= 1) m = fmaxf(m, __shfl_xor_sync(0xffffffffu, m, d));
    float l = 0.f;
    for (int t = lane; t < deg; t += 32) {
        float p = __expf(sc[wid][t] - m);
        sc[wid][t] = p;
        l += p;
    }
#pragma unroll
    for (int d = 16; d; d >>= 1) l += __shfl_xor_sync(0xffffffffu, l, d);
    float linv = 1.0f / l;
    __syncwarp();

    // ---- weighted V: 2 neighbors per warp-iter, float4 per lane ----
    {
        int half = lane >> 4;            // 0 or 1
        int chBase = (lane & 15) * 4;
        size_t vOff = (size_t)wid * HEAD_DIM + chBase;
        float4 acc = make_float4(0.f, 0.f, 0.f, 0.f);
        for (int t = 0; t < deg; t += 2) {
            int tt = t + half;
            bool valid = (tt < deg);
            int n = nbr[valid ? tt : 0];
            float s = valid ? sc[wid][tt] : 0.f;
            float4 vv = *(const float4*)(v + (size_t)n * H_CH + vOff);
            acc.x += s * vv.x; acc.y += s * vv.y;
            acc.z += s * vv.z; acc.w += s * vv.w;
        }
        acc.x += __shfl_xor_sync(0xffffffffu, acc.x, 16);
        acc.y += __shfl_xor_sync(0xffffffffu, acc.y, 16);
        acc.z += __shfl_xor_sync(0xffffffffu, acc.z, 16);
        acc.w += __shfl_xor_sync(0xffffffffu, acc.w, 16);
        if (half == 0) {
            float4 r = make_float4(acc.x * linv, acc.y * linv, acc.z * linv, acc.w * linv);
            *(float4*)(out + (size_t)i * H_CH + vOff) = r;
        }
    }
}

// ---------------- launch ----------------
extern "C" void kernel_launch(void* const* d_in, const int* in_sizes, int n_in,
                              void* d_out, int out_size) {
    const float* x  = (const float*)d_in[0];
    const void*  ei = d_in[1];
    const float* Wq = (const float*)d_in[2];
    const float* bq = (const float*)d_in[3];
    const float* Wk = (const float*)d_in[4];
    const float* bk = (const float*)d_in[5];
    const float* Wv = (const float*)d_in[6];
    const float* bv = (const float*)d_in[7];
    const float* Wo = (const float*)d_in[8];
    const float* bo = (const float*)d_in[9];
    float* out = (float*)d_out;

    float *qp, *kp, *vp, *ap;
    cudaGetSymbolAddress((void**)&qp, g_q);
    cudaGetSymbolAddress((void**)&kp, g_k);
    cudaGetSymbolAddress((void**)&vp, g_v);
    cudaGetSymbolAddress((void**)&ap, g_attn);

    // raise dynamic smem limit (host-side attribute, not a stream op; idempotent)
    cudaFuncSetAttribute(gemm_tf32_kernel,
                         cudaFuncAttributeMaxDynamicSharedMemorySize, GEMM_SMEM_BYTES);

    detect_dtype_kernel<<<1, 128>>>((const unsigned*)ei);
    zero_bitmap_kernel<<<512, 256>>>();
    scatter_edges_kernel<<<(E_EDGES + 255) / 256, 256>>>(ei);

    dim3 qkv_grid(H_CH / 64, N_NODES / 128, 3);
    gemm_tf32_kernel<<<qkv_grid, 256, GEMM_SMEM_BYTES>>>(qp, kp, vp, x, Wq, Wk, Wv, bq, bk, bv);

    attn_kernel<<<N_NODES, 128>>>(ap, qp, kp, vp);

    dim3 o_grid(H_CH / 64, N_NODES / 128, 1);
    gemm_tf32_kernel<<<o_grid, 256, GEMM_SMEM_BYTES>>>(out, out, out, ap, Wo, Wo, Wo, bo, bo, bo);
}

// round 11
// speedup vs baseline: 3.5804x; 1.0594x over previous
#include <cuda_runtime.h>
#include <cuda_fp16.h>
#include <stdint.h>
#include <math.h>

#define N_NODES 8192
#define H_CH 256
#define HEADS 4
#define HEAD_DIM 64
#define E_EDGES 262144
#define WORDS_PER_ROW (N_NODES / 32)   // 256
#define CAP 256

// ---------------- device scratch ----------------
__device__ __align__(128) float   g_q[N_NODES * H_CH];
__device__ __align__(128) float   g_k[N_NODES * H_CH];
__device__ __align__(128) float   g_v[N_NODES * H_CH];
__device__ __align__(128) __half  g_vh[N_NODES * H_CH];
__device__ __align__(128) float   g_attn[N_NODES * H_CH];
__device__ unsigned g_bitmap[N_NODES * WORDS_PER_ROW];
__device__ int      g_is64;

// ---------------- edge dtype detection (parallel) ----------------
__global__ void detect_dtype_kernel(const unsigned* __restrict__ ei_words) {
    __shared__ int bad[4];
    int tid = threadIdx.x;                 // 128 threads
    unsigned v = ei_words[2 * tid + 1];    // high half if int64
    unsigned b = __ballot_sync(0xffffffffu, v != 0u);
    if ((tid & 31) == 0) bad[tid >> 5] = (b != 0u);
    __syncthreads();
    if (tid == 0) g_is64 = !(bad[0] | bad[1] | bad[2] | bad[3]);
}

// ---------------- bitmap zero ----------------
__global__ void zero_bitmap_kernel() {
    int idx = blockIdx.x * blockDim.x + threadIdx.x;
    int total = N_NODES * WORDS_PER_ROW;
    for (int i = idx; i < total; i += gridDim.x * blockDim.x)
        g_bitmap[i] = 0u;
}

// ---------------- edge scatter ----------------
__global__ void scatter_edges_kernel(const void* __restrict__ ei_raw) {
    int e = blockIdx.x * blockDim.x + threadIdx.x;
    if (e >= E_EDGES) return;
    int r, c;
    if (g_is64) {
        const long long* ei = (const long long*)ei_raw;
        r = (int)ei[e];
        c = (int)ei[E_EDGES + e];
    } else {
        const int* ei = (const int*)ei_raw;
        r = ei[e];
        c = ei[E_EDGES + e];
    }
    if ((unsigned)r < N_NODES && (unsigned)c < N_NODES)
        atomicOr(&g_bitmap[r * WORDS_PER_ROW + (c >> 5)], 1u << (c & 31));
}

// ---------------- V fp32 -> fp16 conversion (halves attn V traffic) ----------
__global__ void cvt_v_f16_kernel(const float* __restrict__ v,
                                 __half* __restrict__ vh) {
    int i = blockIdx.x * blockDim.x + threadIdx.x;   // one float4 per thread
    const int total4 = N_NODES * H_CH / 4;
    if (i >= total4) return;
    float4 f = ((const float4*)v)[i];
    __half2 lo = __floats2half2_rn(f.x, f.y);
    __half2 hi = __floats2half2_rn(f.z, f.w);
    uint2 packed;
    packed.x = *(uint32_t*)&lo;
    packed.y = *(uint32_t*)&hi;
    ((uint2*)vh)[i] = packed;
}

// ---------------- tf32 tensor-core GEMM (double-buffered, 32x32 warp tiles) ----
#define SM_STRIDE 36
#define A_WORDS (128 * SM_STRIDE)
#define B_WORDS (64 * SM_STRIDE)
#define GEMM_SMEM_BYTES (2 * (A_WORDS + B_WORDS) * 4)   // 55296

__device__ __forceinline__ uint32_t f2tf32(float f) {
    uint32_t u;
    asm("cvt.rna.tf32.f32 %0, %1;" : "=r"(u) : "f"(f));
    return u;
}

__global__ __launch_bounds__(256) void gemm_tf32_kernel(
        float* __restrict__ Y0, float* __restrict__ Y1, float* __restrict__ Y2,
        const float* __restrict__ A,
        const float* __restrict__ W0, const float* __restrict__ W1, const float* __restrict__ W2,
        const float* __restrict__ b0p, const float* __restrict__ b1p, const float* __restrict__ b2p) {
    const int M_K = 256;
    extern __shared__ __align__(16) uint32_t smem[];
    uint32_t* AsBuf[2] = { smem, smem + A_WORDS };
    uint32_t* BsBuf[2] = { smem + 2 * A_WORDS, smem + 2 * A_WORDS + B_WORDS };

    int z = blockIdx.z;
    float* Y = (z == 0) ? Y0 : (z == 1) ? Y1 : Y2;
    const float* W = (z == 0) ? W0 : (z == 1) ? W1 : W2;
    const float* bias = (z == 0) ? b0p : (z == 1) ? b1p : b2p;

    int tid = threadIdx.x;
    int lane = tid & 31;
    int warp = tid >> 5;
    int wm = warp & 3;               // M sub-tile (32 rows)
    int wn = warp >> 2;              // N sub-tile (32 cols)
    int mBase = blockIdx.y * 128;
    int nBase = blockIdx.x * 64;

    float c[8][4];
#pragma unroll
    for (int i = 0; i < 8; i++)
#pragma unroll
        for (int j = 0; j < 4; j++) c[i][j] = 0.f;

    int a_row = lane & 15;
    int a_col = (lane >> 4) << 2;
    int b_row = (lane & 7) | ((lane >> 1) & 8);
    int b_col = (lane >> 1) & 4;

    uint32_t as_base = (uint32_t)__cvta_generic_to_shared(smem);
    uint32_t bs_base = as_base + 2u * A_WORDS * 4u;
    uint32_t a_addr0 = as_base + ((wm * 32 + a_row) * SM_STRIDE + a_col) * 4u;
    uint32_t a_addr1 = as_base + ((wm * 32 + 16 + a_row) * SM_STRIDE + a_col) * 4u;
    uint32_t b_addr0 = bs_base + ((wn * 32 + b_row) * SM_STRIDE + b_col) * 4u;
    uint32_t b_addr1 = bs_base + ((wn * 32 + 16 + b_row) * SM_STRIDE + b_col) * 4u;

    int ld_row = tid >> 3;           // 0..31
    int ld_col = (tid & 7) * 4;      // 0..28

    const float* aSrc = &A[(size_t)(mBase + ld_row) * M_K + ld_col];
    const float* bSrc = &W[(size_t)(nBase + ld_row) * M_K + ld_col];

    float4 aReg[4], bReg[2];
#pragma unroll
    for (int p = 0; p < 4; p++) aReg[p] = *(const float4*)(aSrc + (size_t)p * 32 * M_K);
#pragma unroll
    for (int p = 0; p < 2; p++) bReg[p] = *(const float4*)(bSrc + (size_t)p * 32 * M_K);

    for (int kt = 0; kt < 8; kt++) {
        int buf = kt & 1;
#pragma unroll
        for (int p = 0; p < 4; p++) {
            uint32_t* dst = &AsBuf[buf][(ld_row + p * 32) * SM_STRIDE + ld_col];
            dst[0] = f2tf32(aReg[p].x); dst[1] = f2tf32(aReg[p].y);
            dst[2] = f2tf32(aReg[p].z); dst[3] = f2tf32(aReg[p].w);
        }
#pragma unroll
        for (int p = 0; p < 2; p++) {
            uint32_t* dst = &BsBuf[buf][(ld_row + p * 32) * SM_STRIDE + ld_col];
            dst[0] = f2tf32(bReg[p].x); dst[1] = f2tf32(bReg[p].y);
            dst[2] = f2tf32(bReg[p].z); dst[3] = f2tf32(bReg[p].w);
        }
        __syncthreads();

        if (kt < 7) {
            int koff = (kt + 1) * 32;
#pragma unroll
            for (int p = 0; p < 4; p++) aReg[p] = *(const float4*)(aSrc + (size_t)p * 32 * M_K + koff);
#pragma unroll
            for (int p = 0; p < 2; p++) bReg[p] = *(const float4*)(bSrc + (size_t)p * 32 * M_K + koff);
        }

        uint32_t aBufOff = (uint32_t)buf * (A_WORDS * 4u);
        uint32_t bBufOff = (uint32_t)buf * (B_WORDS * 4u);
#pragma unroll
        for (int ks = 0; ks < 4; ks++) {
            uint32_t kc4 = (uint32_t)(ks * 8) * 4u;
            uint32_t a0, a1, a2, a3, a4, a5, a6, a7;
            asm volatile(
                "ldmatrix.sync.aligned.m8n8.x4.shared.b16 {%0,%1,%2,%3}, [%4];"
                : "=r"(a0), "=r"(a1), "=r"(a2), "=r"(a3)
                : "r"(a_addr0 + aBufOff + kc4));
            asm volatile(
                "ldmatrix.sync.aligned.m8n8.x4.shared.b16 {%0,%1,%2,%3}, [%4];"
                : "=r"(a4), "=r"(a5), "=r"(a6), "=r"(a7)
                : "r"(a_addr1 + aBufOff + kc4));
            uint32_t bb0, bb1, bb2, bb3, bb4, bb5, bb6, bb7;
            asm volatile(
                "ldmatrix.sync.aligned.m8n8.x4.shared.b16 {%0,%1,%2,%3}, [%4];"
                : "=r"(bb0), "=r"(bb1), "=r"(bb2), "=r"(bb3)
                : "r"(b_addr0 + bBufOff + kc4));
            asm volatile(
                "ldmatrix.sync.aligned.m8n8.x4.shared.b16 {%0,%1,%2,%3}, [%4];"
                : "=r"(bb4), "=r"(bb5), "=r"(bb6), "=r"(bb7)
                : "r"(b_addr1 + bBufOff + kc4));

#define MMA4(CI, AA0, AA1, AA2, AA3, B0, B1)                              \
            asm volatile(                                                 \
                "mma.sync.aligned.m16n8k8.row.col.f32.tf32.tf32.f32 "     \
                "{%0,%1,%2,%3}, {%4,%5,%6,%7}, {%8,%9}, {%0,%1,%2,%3};"   \
                : "+f"(c[CI][0]), "+f"(c[CI][1]), "+f"(c[CI][2]), "+f"(c[CI][3]) \
                : "r"(AA0), "r"(AA1), "r"(AA2), "r"(AA3), "r"(B0), "r"(B1))
            MMA4(0, a0, a1, a2, a3, bb0, bb1);
            MMA4(1, a0, a1, a2, a3, bb2, bb3);
            MMA4(2, a0, a1, a2, a3, bb4, bb5);
            MMA4(3, a0, a1, a2, a3, bb6, bb7);
            MMA4(4, a4, a5, a6, a7, bb0, bb1);
            MMA4(5, a4, a5, a6, a7, bb2, bb3);
            MMA4(6, a4, a5, a6, a7, bb4, bb5);
            MMA4(7, a4, a5, a6, a7, bb6, bb7);
#undef MMA4
        }
    }

    int rowB = mBase + wm * 32 + (lane >> 2);
#pragma unroll
    for (int mt = 0; mt < 2; mt++) {
#pragma unroll
        for (int g = 0; g < 4; g++) {
            int ci = mt * 4 + g;
            int row = rowB + mt * 16;
            int col = nBase + wn * 32 + g * 8 + (lane & 3) * 2;
            float b0 = bias[col], b1 = bias[col + 1];
            *(float2*)&Y[(size_t)row * M_K + col] = make_float2(c[ci][0] + b0, c[ci][1] + b1);
            *(float2*)&Y[(size_t)(row + 8) * M_K + col] = make_float2(c[ci][2] + b0, c[ci][3] + b1);
        }
    }
}

// ---------------- sparse masked attention: warp w = head w ----------------
__global__ __launch_bounds__(128) void attn_kernel(
        float* __restrict__ out,
        const float* __restrict__ q,
        const float* __restrict__ k,
        const __half* __restrict__ vh) {
    __shared__ unsigned short nbr[CAP];
    __shared__ float sc[HEADS][CAP];
    __shared__ int warpSum[4];
    __shared__ int warpBase[4];
    __shared__ int deg_s;

    int i = blockIdx.x;
    int tid = threadIdx.x;          // 128 threads
    int lane = tid & 31;
    int wid = tid >> 5;             // = head index

    // ---- deterministic neighbor gather ----
    uint2 wpair = *(const uint2*)&g_bitmap[i * WORDS_PER_ROW + tid * 2];
    unsigned w0 = wpair.x, w1 = wpair.y;
    int c = __popc(w0) + __popc(w1);
    int incl = c;
#pragma unroll
    for (int d = 1; d < 32; d <<= 1) {
        int n_ = __shfl_up_sync(0xffffffffu, incl, d);
        if (lane >= d) incl += n_;
    }
    if (lane == 31) warpSum[wid] = incl;
    __syncthreads();
    if (tid < 4) {
        int e = 0;
        for (int j2 = 0; j2 < tid; j2++) e += warpSum[j2];
        warpBase[tid] = e;
        if (tid == 3) deg_s = e + warpSum[3];
    }
    __syncthreads();
    int off = warpBase[wid] + (incl - c);
    int base0 = tid * 64;
    while (w0) {
        int b = __ffs(w0) - 1;
        w0 &= w0 - 1;
        if (off < CAP) nbr[off] = (unsigned short)(base0 + b);
        off++;
    }
    while (w1) {
        int b = __ffs(w1) - 1;
        w1 &= w1 - 1;
        if (off < CAP) nbr[off] = (unsigned short)(base0 + 32 + b);
        off++;
    }
    __syncthreads();
    int deg = min(deg_s, CAP);

    // ---- scores: 4 neighbors per warp-iter; 8-lane groups, 3-level reduce ----
    {
        int sub = lane >> 3;
        int chBase = (lane & 7) * 8;
        const float* qRow = q + (size_t)i * H_CH + wid * HEAD_DIM + chBase;
        float4 q0 = *(const float4*)qRow;
        float4 q1 = *(const float4*)(qRow + 4);
        for (int j = 0; j < deg; j += 4) {
            int jj = j + sub;
            bool valid = (jj < deg);
            int n = nbr[valid ? jj : 0];
            const float* kRow = k + (size_t)n * H_CH + wid * HEAD_DIM + chBase;
            float4 k0 = *(const float4*)kRow;
            float4 k1 = *(const float4*)(kRow + 4);
            float p = k0.x * q0.x + k0.y * q0.y + k0.z * q0.z + k0.w * q0.w
                    + k1.x * q1.x + k1.y * q1.y + k1.z * q1.z + k1.w * q1.w;
            p += __shfl_xor_sync(0xffffffffu, p, 1);
            p += __shfl_xor_sync(0xffffffffu, p, 2);
            p += __shfl_xor_sync(0xffffffffu, p, 4);
            if (valid && (lane & 7) == 0) sc[wid][jj] = p * 0.125f;
        }
    }
    __syncwarp();

    // ---- warp-local softmax over sc[wid][0..deg) ----
    float m = -1e30f;
    for (int t = lane; t < deg; t += 32) m = fmaxf(m, sc[wid][t]);
#pragma unroll
    for (int d = 16; d; d >>= 1) m = fmaxf(m, __shfl_xor_sync(0xffffffffu, m, d));
    float l = 0.f;
    for (int t = lane; t < deg; t += 32) {
        float p = __expf(sc[wid][t] - m);
        sc[wid][t] = p;
        l += p;
    }
#pragma unroll
    for (int d = 16; d; d >>= 1) l += __shfl_xor_sync(0xffffffffu, l, d);
    float linv = 1.0f / l;
    __syncwarp();

    // ---- weighted V (fp16): 2 neighbors per warp-iter, 4 ch (8B) per lane ----
    {
        int half = lane >> 4;            // 0 or 1
        int chBase = (lane & 15) * 4;
        size_t vOff = (size_t)wid * HEAD_DIM + chBase;   // fp16 element offset
        float4 acc = make_float4(0.f, 0.f, 0.f, 0.f);
        for (int t = 0; t < deg; t += 2) {
            int tt = t + half;
            bool valid = (tt < deg);
            int n = nbr[valid ? tt : 0];
            float s = valid ? sc[wid][tt] : 0.f;
            uint2 raw = *(const uint2*)(vh + (size_t)n * H_CH + vOff);
            __half2 p0 = *(__half2*)&raw.x;
            __half2 p1 = *(__half2*)&raw.y;
            float2 f0 = __half22float2(p0);
            float2 f1 = __half22float2(p1);
            acc.x += s * f0.x; acc.y += s * f0.y;
            acc.z += s * f1.x; acc.w += s * f1.y;
        }
        acc.x += __shfl_xor_sync(0xffffffffu, acc.x, 16);
        acc.y += __shfl_xor_sync(0xffffffffu, acc.y, 16);
        acc.z += __shfl_xor_sync(0xffffffffu, acc.z, 16);
        acc.w += __shfl_xor_sync(0xffffffffu, acc.w, 16);
        if (half == 0) {
            float4 r = make_float4(acc.x * linv, acc.y * linv, acc.z * linv, acc.w * linv);
            *(float4*)(out + (size_t)i * H_CH + vOff) = r;
        }
    }
}

// ---------------- launch ----------------
extern "C" void kernel_launch(void* const* d_in, const int* in_sizes, int n_in,
                              void* d_out, int out_size) {
    const float* x  = (const float*)d_in[0];
    const void*  ei = d_in[1];
    const float* Wq = (const float*)d_in[2];
    const float* bq = (const float*)d_in[3];
    const float* Wk = (const float*)d_in[4];
    const float* bk = (const float*)d_in[5];
    const float* Wv = (const float*)d_in[6];
    const float* bv = (const float*)d_in[7];
    const float* Wo = (const float*)d_in[8];
    const float* bo = (const float*)d_in[9];
    float* out = (float*)d_out;

    float *qp, *kp, *vp, *ap;
    __half* vhp;
    cudaGetSymbolAddress((void**)&qp, g_q);
    cudaGetSymbolAddress((void**)&kp, g_k);
    cudaGetSymbolAddress((void**)&vp, g_v);
    cudaGetSymbolAddress((void**)&vhp, g_vh);
    cudaGetSymbolAddress((void**)&ap, g_attn);

    cudaFuncSetAttribute(gemm_tf32_kernel,
                         cudaFuncAttributeMaxDynamicSharedMemorySize, GEMM_SMEM_BYTES);

    detect_dtype_kernel<<<1, 128>>>((const unsigned*)ei);
    zero_bitmap_kernel<<<512, 256>>>();
    scatter_edges_kernel<<<(E_EDGES + 255) / 256, 256>>>(ei);

    dim3 qkv_grid(H_CH / 64, N_NODES / 128, 3);
    gemm_tf32_kernel<<<qkv_grid, 256, GEMM_SMEM_BYTES>>>(qp, kp, vp, x, Wq, Wk, Wv, bq, bk, bv);

    cvt_v_f16_kernel<<<(N_NODES * H_CH / 4 + 255) / 256, 256>>>(vp, vhp);

    attn_kernel<<<N_NODES, 128>>>(ap, qp, kp, vhp);

    dim3 o_grid(H_CH / 64, N_NODES / 128, 1);
    gemm_tf32_kernel<<<o_grid, 256, GEMM_SMEM_BYTES>>>(out, out, out, ap, Wo, Wo, Wo, bo, bo, bo);
}

// round 12
// speedup vs baseline: 3.9111x; 1.0924x over previous
#include <cuda_runtime.h>
#include <cuda_fp16.h>
#include <stdint.h>
#include <math.h>

#define N_NODES 8192
#define H_CH 256
#define HEADS 4
#define HEAD_DIM 64
#define E_EDGES 262144
#define WORDS_PER_ROW (N_NODES / 32)   // 256
#define CAP 256

// ---------------- device scratch ----------------
__device__ __align__(128) float   g_xt[N_NODES * H_CH];    // x pre-rounded to tf32
__device__ __align__(128) float   g_wt[4][H_CH * H_CH];    // Wq,Wk,Wv,Wo tf32
__device__ __align__(128) float   g_q[N_NODES * H_CH];
__device__ __align__(128) __half  g_kh[N_NODES * H_CH];
__device__ __align__(128) __half  g_vh[N_NODES * H_CH];
__device__ __align__(128) float   g_attn[N_NODES * H_CH];  // tf32-rounded by attn
__device__ unsigned g_bitmap[N_NODES * WORDS_PER_ROW];
__device__ int      g_is64;

__device__ __forceinline__ uint32_t f2tf32(float f) {
    uint32_t u;
    asm("cvt.rna.tf32.f32 %0, %1;" : "=r"(u) : "f"(f));
    return u;
}

// ---------------- edge dtype detection (parallel) ----------------
__global__ void detect_dtype_kernel(const unsigned* __restrict__ ei_words) {
    __shared__ int bad[4];
    int tid = threadIdx.x;                 // 128 threads
    unsigned v = ei_words[2 * tid + 1];
    unsigned b = __ballot_sync(0xffffffffu, v != 0u);
    if ((tid & 31) == 0) bad[tid >> 5] = (b != 0u);
    __syncthreads();
    if (tid == 0) g_is64 = !(bad[0] | bad[1] | bad[2] | bad[3]);
}

// ---------------- bitmap zero ----------------
__global__ void zero_bitmap_kernel() {
    int idx = blockIdx.x * blockDim.x + threadIdx.x;
    int total = N_NODES * WORDS_PER_ROW;
    for (int i = idx; i < total; i += gridDim.x * blockDim.x)
        g_bitmap[i] = 0u;
}

// ---------------- edge scatter ----------------
__global__ void scatter_edges_kernel(const void* __restrict__ ei_raw) {
    int e = blockIdx.x * blockDim.x + threadIdx.x;
    if (e >= E_EDGES) return;
    int r, c;
    if (g_is64) {
        const long long* ei = (const long long*)ei_raw;
        r = (int)ei[e];
        c = (int)ei[E_EDGES + e];
    } else {
        const int* ei = (const int*)ei_raw;
        r = ei[e];
        c = ei[E_EDGES + e];
    }
    if ((unsigned)r < N_NODES && (unsigned)c < N_NODES)
        atomicOr(&g_bitmap[r * WORDS_PER_ROW + (c >> 5)], 1u << (c & 31));
}

// ---------------- tf32 pre-rounding passes ----------------
__global__ void cvt_x_tf32_kernel(const float* __restrict__ x) {
    int i = blockIdx.x * blockDim.x + threadIdx.x;   // one float4
    const int total4 = N_NODES * H_CH / 4;
    if (i >= total4) return;
    float4 f = ((const float4*)x)[i];
    uint4 o;
    o.x = f2tf32(f.x); o.y = f2tf32(f.y); o.z = f2tf32(f.z); o.w = f2tf32(f.w);
    ((uint4*)g_xt)[i] = o;
}

__global__ void cvt_w_tf32_kernel(const float* __restrict__ w0,
                                  const float* __restrict__ w1,
                                  const float* __restrict__ w2,
                                  const float* __restrict__ w3) {
    int z = blockIdx.y;
    const float* w = (z == 0) ? w0 : (z == 1) ? w1 : (z == 2) ? w2 : w3;
    int i = blockIdx.x * blockDim.x + threadIdx.x;   // one float4
    const int total4 = H_CH * H_CH / 4;
    if (i >= total4) return;
    float4 f = ((const float4*)w)[i];
    uint4 o;
    o.x = f2tf32(f.x); o.y = f2tf32(f.y); o.z = f2tf32(f.z); o.w = f2tf32(f.w);
    ((uint4*)g_wt[z])[i] = o;
}

// ---------------- tf32 GEMM: cp.async double-buffered, 32x32 warp tiles -------
// Inputs A, W already tf32-rounded. z==0 writes float; z==1/2 write half.
#define SM_STRIDE 36
#define A_WORDS (128 * SM_STRIDE)
#define B_WORDS (64 * SM_STRIDE)
#define GEMM_SMEM_BYTES (2 * (A_WORDS + B_WORDS) * 4)   // 55296

__device__ __forceinline__ void cpa16(uint32_t dst, const float* src) {
    asm volatile("cp.async.cg.shared.global [%0], [%1], 16;" :: "r"(dst), "l"(src));
}

__global__ __launch_bounds__(256) void gemm_tf32_kernel(
        float* __restrict__ Yq, __half* __restrict__ Ykh, __half* __restrict__ Yvh,
        const float* __restrict__ A,
        const float* __restrict__ W0, const float* __restrict__ W1, const float* __restrict__ W2,
        const float* __restrict__ b0p, const float* __restrict__ b1p, const float* __restrict__ b2p) {
    const int M_K = 256;
    extern __shared__ __align__(16) uint32_t smem[];

    int z = blockIdx.z;
    const float* W = (z == 0) ? W0 : (z == 1) ? W1 : W2;
    const float* bias = (z == 0) ? b0p : (z == 1) ? b1p : b2p;

    int tid = threadIdx.x;
    int lane = tid & 31;
    int warp = tid >> 5;
    int wm = warp & 3;
    int wn = warp >> 2;
    int mBase = blockIdx.y * 128;
    int nBase = blockIdx.x * 64;

    float c[8][4];
#pragma unroll
    for (int i = 0; i < 8; i++)
#pragma unroll
        for (int j = 0; j < 4; j++) c[i][j] = 0.f;

    int a_row = lane & 15;
    int a_col = (lane >> 4) << 2;
    int b_row = (lane & 7) | ((lane >> 1) & 8);
    int b_col = (lane >> 1) & 4;

    uint32_t as_base = (uint32_t)__cvta_generic_to_shared(smem);
    uint32_t bs_base = as_base + 2u * A_WORDS * 4u;
    uint32_t a_addr0 = as_base + ((wm * 32 + a_row) * SM_STRIDE + a_col) * 4u;
    uint32_t a_addr1 = as_base + ((wm * 32 + 16 + a_row) * SM_STRIDE + a_col) * 4u;
    uint32_t b_addr0 = bs_base + ((wn * 32 + b_row) * SM_STRIDE + b_col) * 4u;
    uint32_t b_addr1 = bs_base + ((wn * 32 + 16 + b_row) * SM_STRIDE + b_col) * 4u;

    int ld_row = tid >> 3;           // 0..31
    int ld_col = (tid & 7) * 4;      // 0..28

    const float* aSrc = &A[(size_t)(mBase + ld_row) * M_K + ld_col];
    const float* bSrc = &W[(size_t)(nBase + ld_row) * M_K + ld_col];

    // per-buffer smem byte offsets for this thread's copy destinations
    uint32_t aDst = as_base + (uint32_t)(ld_row * SM_STRIDE + ld_col) * 4u;
    uint32_t bDst = bs_base + (uint32_t)(ld_row * SM_STRIDE + ld_col) * 4u;

#define ISSUE_CHUNK(KT)                                                        \
    do {                                                                       \
        int _buf = (KT) & 1;                                                   \
        uint32_t _ao = (uint32_t)_buf * (A_WORDS * 4u);                        \
        uint32_t _bo = (uint32_t)_buf * (B_WORDS * 4u);                        \
        int _ko = (KT) * 32;                                                   \
        cpa16(aDst + _ao + 0u * 32u * SM_STRIDE * 4u, aSrc + (size_t)0 * 32 * M_K + _ko); \
        cpa16(aDst + _ao + 1u * 32u * SM_STRIDE * 4u, aSrc + (size_t)1 * 32 * M_K + _ko); \
        cpa16(aDst + _ao + 2u * 32u * SM_STRIDE * 4u, aSrc + (size_t)2 * 32 * M_K + _ko); \
        cpa16(aDst + _ao + 3u * 32u * SM_STRIDE * 4u, aSrc + (size_t)3 * 32 * M_K + _ko); \
        cpa16(bDst + _bo + 0u * 32u * SM_STRIDE * 4u, bSrc + (size_t)0 * 32 * M_K + _ko); \
        cpa16(bDst + _bo + 1u * 32u * SM_STRIDE * 4u, bSrc + (size_t)1 * 32 * M_K + _ko); \
        asm volatile("cp.async.commit_group;" ::: "memory");                   \
    } while (0)

    ISSUE_CHUNK(0);

    for (int kt = 0; kt < 8; kt++) {
        asm volatile("cp.async.wait_group 0;" ::: "memory");
        __syncthreads();
        if (kt < 7) ISSUE_CHUNK(kt + 1);

        int buf = kt & 1;
        uint32_t aBufOff = (uint32_t)buf * (A_WORDS * 4u);
        uint32_t bBufOff = (uint32_t)buf * (B_WORDS * 4u);
#pragma unroll
        for (int ks = 0; ks < 4; ks++) {
            uint32_t kc4 = (uint32_t)(ks * 8) * 4u;
            uint32_t a0, a1, a2, a3, a4, a5, a6, a7;
            asm volatile(
                "ldmatrix.sync.aligned.m8n8.x4.shared.b16 {%0,%1,%2,%3}, [%4];"
                : "=r"(a0), "=r"(a1), "=r"(a2), "=r"(a3)
                : "r"(a_addr0 + aBufOff + kc4));
            asm volatile(
                "ldmatrix.sync.aligned.m8n8.x4.shared.b16 {%0,%1,%2,%3}, [%4];"
                : "=r"(a4), "=r"(a5), "=r"(a6), "=r"(a7)
                : "r"(a_addr1 + aBufOff + kc4));
            uint32_t bb0, bb1, bb2, bb3, bb4, bb5, bb6, bb7;
            asm volatile(
                "ldmatrix.sync.aligned.m8n8.x4.shared.b16 {%0,%1,%2,%3}, [%4];"
                : "=r"(bb0), "=r"(bb1), "=r"(bb2), "=r"(bb3)
                : "r"(b_addr0 + bBufOff + kc4));
            asm volatile(
                "ldmatrix.sync.aligned.m8n8.x4.shared.b16 {%0,%1,%2,%3}, [%4];"
                : "=r"(bb4), "=r"(bb5), "=r"(bb6), "=r"(bb7)
                : "r"(b_addr1 + bBufOff + kc4));

#define MMA4(CI, AA0, AA1, AA2, AA3, B0, B1)                              \
            asm volatile(                                                 \
                "mma.sync.aligned.m16n8k8.row.col.f32.tf32.tf32.f32 "     \
                "{%0,%1,%2,%3}, {%4,%5,%6,%7}, {%8,%9}, {%0,%1,%2,%3};"   \
                : "+f"(c[CI][0]), "+f"(c[CI][1]), "+f"(c[CI][2]), "+f"(c[CI][3]) \
                : "r"(AA0), "r"(AA1), "r"(AA2), "r"(AA3), "r"(B0), "r"(B1))
            MMA4(0, a0, a1, a2, a3, bb0, bb1);
            MMA4(1, a0, a1, a2, a3, bb2, bb3);
            MMA4(2, a0, a1, a2, a3, bb4, bb5);
            MMA4(3, a0, a1, a2, a3, bb6, bb7);
            MMA4(4, a4, a5, a6, a7, bb0, bb1);
            MMA4(5, a4, a5, a6, a7, bb2, bb3);
            MMA4(6, a4, a5, a6, a7, bb4, bb5);
            MMA4(7, a4, a5, a6, a7, bb6, bb7);
#undef MMA4
        }
    }
#undef ISSUE_CHUNK

    // epilogue: z==0 -> float out (Yq); z==1 -> half out (Ykh); z==2 -> half (Yvh)
    int rowB = mBase + wm * 32 + (lane >> 2);
    __half* Yh = (z == 1) ? Ykh : Yvh;
#pragma unroll
    for (int mt = 0; mt < 2; mt++) {
#pragma unroll
        for (int g = 0; g < 4; g++) {
            int ci = mt * 4 + g;
            int row = rowB + mt * 16;
            int col = nBase + wn * 32 + g * 8 + (lane & 3) * 2;
            float b0 = bias[col], b1 = bias[col + 1];
            float r00 = c[ci][0] + b0, r01 = c[ci][1] + b1;
            float r10 = c[ci][2] + b0, r11 = c[ci][3] + b1;
            if (z == 0) {
                *(float2*)&Yq[(size_t)row * M_K + col] = make_float2(r00, r01);
                *(float2*)&Yq[(size_t)(row + 8) * M_K + col] = make_float2(r10, r11);
            } else {
                *(__half2*)&Yh[(size_t)row * M_K + col] = __floats2half2_rn(r00, r01);
                *(__half2*)&Yh[(size_t)(row + 8) * M_K + col] = __floats2half2_rn(r10, r11);
            }
        }
    }
}

// ---------------- sparse masked attention: warp w = head w (K,V fp16) ---------
__global__ __launch_bounds__(128) void attn_kernel(
        float* __restrict__ out,
        const float* __restrict__ q,
        const __half* __restrict__ kh,
        const __half* __restrict__ vh) {
    __shared__ unsigned short nbr[CAP];
    __shared__ float sc[HEADS][CAP];
    __shared__ int warpSum[4];
    __shared__ int warpBase[4];
    __shared__ int deg_s;

    int i = blockIdx.x;
    int tid = threadIdx.x;          // 128 threads
    int lane = tid & 31;
    int wid = tid >> 5;             // head index

    // ---- deterministic neighbor gather ----
    uint2 wpair = *(const uint2*)&g_bitmap[i * WORDS_PER_ROW + tid * 2];
    unsigned w0 = wpair.x, w1 = wpair.y;
    int c = __popc(w0) + __popc(w1);
    int incl = c;
#pragma unroll
    for (int d = 1; d < 32; d <<= 1) {
        int n_ = __shfl_up_sync(0xffffffffu, incl, d);
        if (lane >= d) incl += n_;
    }
    if (lane == 31) warpSum[wid] = incl;
    __syncthreads();
    if (tid < 4) {
        int e = 0;
        for (int j2 = 0; j2 < tid; j2++) e += warpSum[j2];
        warpBase[tid] = e;
        if (tid == 3) deg_s = e + warpSum[3];
    }
    __syncthreads();
    int off = warpBase[wid] + (incl - c);
    int base0 = tid * 64;
    while (w0) {
        int b = __ffs(w0) - 1;
        w0 &= w0 - 1;
        if (off < CAP) nbr[off] = (unsigned short)(base0 + b);
        off++;
    }
    while (w1) {
        int b = __ffs(w1) - 1;
        w1 &= w1 - 1;
        if (off < CAP) nbr[off] = (unsigned short)(base0 + 32 + b);
        off++;
    }
    __syncthreads();
    int deg = min(deg_s, CAP);

    // ---- scores: 4 neighbors/warp-iter; 8-lane groups; one uint4 K load ----
    {
        int sub = lane >> 3;
        int chBase = (lane & 7) * 8;
        const float* qRow = q + (size_t)i * H_CH + wid * HEAD_DIM + chBase;
        float4 q0 = *(const float4*)qRow;
        float4 q1 = *(const float4*)(qRow + 4);
        for (int j = 0; j < deg; j += 4) {
            int jj = j + sub;
            bool valid = (jj < deg);
            int n = nbr[valid ? jj : 0];
            uint4 raw = *(const uint4*)(kh + (size_t)n * H_CH + wid * HEAD_DIM + chBase);
            float2 f0 = __half22float2(*(__half2*)&raw.x);
            float2 f1 = __half22float2(*(__half2*)&raw.y);
            float2 f2 = __half22float2(*(__half2*)&raw.z);
            float2 f3 = __half22float2(*(__half2*)&raw.w);
            float p = f0.x * q0.x + f0.y * q0.y + f1.x * q0.z + f1.y * q0.w
                    + f2.x * q1.x + f2.y * q1.y + f3.x * q1.z + f3.y * q1.w;
            p += __shfl_xor_sync(0xffffffffu, p, 1);
            p += __shfl_xor_sync(0xffffffffu, p, 2);
            p += __shfl_xor_sync(0xffffffffu, p, 4);
            if (valid && (lane & 7) == 0) sc[wid][jj] = p * 0.125f;
        }
    }
    __syncwarp();

    // ---- warp-local softmax ----
    float m = -1e30f;
    for (int t = lane; t < deg; t += 32) m = fmaxf(m, sc[wid][t]);
#pragma unroll
    for (int d = 16; d; d >>= 1) m = fmaxf(m, __shfl_xor_sync(0xffffffffu, m, d));
    float l = 0.f;
    for (int t = lane; t < deg; t += 32) {
        float p = __expf(sc[wid][t] - m);
        sc[wid][t] = p;
        l += p;
    }
#pragma unroll
    for (int d = 16; d; d >>= 1) l += __shfl_xor_sync(0xffffffffu, l, d);
    float linv = 1.0f / l;
    __syncwarp();

    // ---- weighted V (fp16): 2 neighbors/warp-iter, 4 ch per lane ----
    {
        int half = lane >> 4;
        int chBase = (lane & 15) * 4;
        size_t vOff = (size_t)wid * HEAD_DIM + chBase;
        float4 acc = make_float4(0.f, 0.f, 0.f, 0.f);
        for (int t = 0; t < deg; t += 2) {
            int tt = t + half;
            bool valid = (tt < deg);
            int n = nbr[valid ? tt : 0];
            float s = valid ? sc[wid][tt] : 0.f;
            uint2 raw = *(const uint2*)(vh + (size_t)n * H_CH + vOff);
            float2 f0 = __half22float2(*(__half2*)&raw.x);
            float2 f1 = __half22float2(*(__half2*)&raw.y);
            acc.x += s * f0.x; acc.y += s * f0.y;
            acc.z += s * f1.x; acc.w += s * f1.y;
        }
        acc.x += __shfl_xor_sync(0xffffffffu, acc.x, 16);
        acc.y += __shfl_xor_sync(0xffffffffu, acc.y, 16);
        acc.z += __shfl_xor_sync(0xffffffffu, acc.z, 16);
        acc.w += __shfl_xor_sync(0xffffffffu, acc.w, 16);
        if (half == 0) {
            // pre-round to tf32 so the O-GEMM can consume raw (no cvt there)
            uint4 r;
            r.x = f2tf32(acc.x * linv);
            r.y = f2tf32(acc.y * linv);
            r.z = f2tf32(acc.z * linv);
            r.w = f2tf32(acc.w * linv);
            *(uint4*)(out + (size_t)i * H_CH + vOff) = r;
        }
    }
}

// ---------------- launch ----------------
extern "C" void kernel_launch(void* const* d_in, const int* in_sizes, int n_in,
                              void* d_out, int out_size) {
    const float* x  = (const float*)d_in[0];
    const void*  ei = d_in[1];
    const float* Wq = (const float*)d_in[2];
    const float* bq = (const float*)d_in[3];
    const float* Wk = (const float*)d_in[4];
    const float* bk = (const float*)d_in[5];
    const float* Wv = (const float*)d_in[6];
    const float* bv = (const float*)d_in[7];
    const float* Wo = (const float*)d_in[8];
    const float* bo = (const float*)d_in[9];
    float* out = (float*)d_out;

    float *xtp, *wtp, *qp, *ap;
    __half *khp, *vhp;
    cudaGetSymbolAddress((void**)&xtp, g_xt);
    cudaGetSymbolAddress((void**)&wtp, g_wt);
    cudaGetSymbolAddress((void**)&qp, g_q);
    cudaGetSymbolAddress((void**)&khp, g_kh);
    cudaGetSymbolAddress((void**)&vhp, g_vh);
    cudaGetSymbolAddress((void**)&ap, g_attn);

    cudaFuncSetAttribute(gemm_tf32_kernel,
                         cudaFuncAttributeMaxDynamicSharedMemorySize, GEMM_SMEM_BYTES);

    detect_dtype_kernel<<<1, 128>>>((const unsigned*)ei);
    zero_bitmap_kernel<<<512, 256>>>();
    scatter_edges_kernel<<<(E_EDGES + 255) / 256, 256>>>(ei);

    // pre-round inputs to tf32
    cvt_x_tf32_kernel<<<(N_NODES * H_CH / 4 + 255) / 256, 256>>>(x);
    dim3 wgrid((H_CH * H_CH / 4 + 255) / 256, 4);
    cvt_w_tf32_kernel<<<wgrid, 256>>>(Wq, Wk, Wv, Wo);

    // fused QKV: z=0 Q (fp32), z=1 K (fp16), z=2 V (fp16)
    dim3 qkv_grid(H_CH / 64, N_NODES / 128, 3);
    gemm_tf32_kernel<<<qkv_grid, 256, GEMM_SMEM_BYTES>>>(
        qp, khp, vhp, xtp,
        wtp + 0 * H_CH * H_CH, wtp + 1 * H_CH * H_CH, wtp + 2 * H_CH * H_CH,
        bq, bk, bv);

    attn_kernel<<<N_NODES, 128>>>(ap, qp, khp, vhp);

    // O-GEMM: z=0 only, float out; A = g_attn (already tf32-rounded)
    dim3 o_grid(H_CH / 64, N_NODES / 128, 1);
    gemm_tf32_kernel<<<o_grid, 256, GEMM_SMEM_BYTES>>>(
        out, khp, vhp, ap,
        wtp + 3 * H_CH * H_CH, wtp + 3 * H_CH * H_CH, wtp + 3 * H_CH * H_CH,
        bo, bo, bo);
}

// round 13
// speedup vs baseline: 4.7568x; 1.2162x over previous
#include <cuda_runtime.h>
#include <cuda_fp16.h>
#include <stdint.h>
#include <math.h>

#define N_NODES 8192
#define H_CH 256
#define HEADS 4
#define HEAD_DIM 64
#define E_EDGES 262144
#define WORDS_PER_ROW (N_NODES / 32)   // 256
#define CAP 256

// ---------------- device scratch ----------------
__device__ __align__(128) __half  g_xh[N_NODES * H_CH];    // x in fp16
__device__ __align__(128) __half  g_wh[4][H_CH * H_CH];    // Wq,Wk,Wv,Wo fp16
__device__ __align__(128) float   g_q[N_NODES * H_CH];
__device__ __align__(128) __half  g_kh[N_NODES * H_CH];
__device__ __align__(128) __half  g_vh[N_NODES * H_CH];
__device__ __align__(128) __half  g_ah[N_NODES * H_CH];    // attn output fp16
__device__ unsigned g_bitmap[N_NODES * WORDS_PER_ROW];
__device__ int      g_is64;

// ---------------- edge dtype detection (parallel) ----------------
__global__ void detect_dtype_kernel(const unsigned* __restrict__ ei_words) {
    __shared__ int bad[4];
    int tid = threadIdx.x;                 // 128 threads
    unsigned v = ei_words[2 * tid + 1];
    unsigned b = __ballot_sync(0xffffffffu, v != 0u);
    if ((tid & 31) == 0) bad[tid >> 5] = (b != 0u);
    __syncthreads();
    if (tid == 0) g_is64 = !(bad[0] | bad[1] | bad[2] | bad[3]);
}

// ---------------- bitmap zero ----------------
__global__ void zero_bitmap_kernel() {
    int idx = blockIdx.x * blockDim.x + threadIdx.x;
    int total = N_NODES * WORDS_PER_ROW;
    for (int i = idx; i < total; i += gridDim.x * blockDim.x)
        g_bitmap[i] = 0u;
}

// ---------------- edge scatter ----------------
__global__ void scatter_edges_kernel(const void* __restrict__ ei_raw) {
    int e = blockIdx.x * blockDim.x + threadIdx.x;
    if (e >= E_EDGES) return;
    int r, c;
    if (g_is64) {
        const long long* ei = (const long long*)ei_raw;
        r = (int)ei[e];
        c = (int)ei[E_EDGES + e];
    } else {
        const int* ei = (const int*)ei_raw;
        r = ei[e];
        c = ei[E_EDGES + e];
    }
    if ((unsigned)r < N_NODES && (unsigned)c < N_NODES)
        atomicOr(&g_bitmap[r * WORDS_PER_ROW + (c >> 5)], 1u << (c & 31));
}

// ---------------- merged fp32 -> fp16 conversion: x + all 4 weights ----------
#define X_F4   (N_NODES * H_CH / 4)            // 524288 float4s
#define W_F4   (H_CH * H_CH / 4)               // 16384 float4s per W
#define TOT_F4 (X_F4 + 4 * W_F4)

__global__ void cvt_all_f16_kernel(const float* __restrict__ x,
                                   const float* __restrict__ w0,
                                   const float* __restrict__ w1,
                                   const float* __restrict__ w2,
                                   const float* __restrict__ w3) {
    for (int i = blockIdx.x * blockDim.x + threadIdx.x; i < TOT_F4;
         i += gridDim.x * blockDim.x) {
        const float* src;
        __half* dst;
        int idx;
        if (i < X_F4) {
            src = x; dst = g_xh; idx = i;
        } else {
            int i2 = i - X_F4;
            int z = i2 >> 14;                  // /16384
            idx = i2 & 16383;
            src = (z == 0) ? w0 : (z == 1) ? w1 : (z == 2) ? w2 : w3;
            dst = g_wh[z];
        }
        float4 f = ((const float4*)src)[idx];
        __half2 lo = __floats2half2_rn(f.x, f.y);
        __half2 hi = __floats2half2_rn(f.z, f.w);
        uint2 packed;
        packed.x = *(uint32_t*)&lo;
        packed.y = *(uint32_t*)&hi;
        ((uint2*)dst)[idx] = packed;
    }
}

// ---------------- fp16 tensor GEMM: Y[M,256] = A[M,256] @ W[256,256]^T + b ----
// m16n8k16 fp16 mma, fp32 accum. 128x64 block tile, 32-k chunks, cp.async
// double buffer (static smem 30.7KB). 8 warps = 4M x 2N of 32x32 tiles.
#define SMH 40                        // half-stride per row (80B, conflict-free)
#define A_HALF (128 * SMH)            // 5120
#define B_HALF (64 * SMH)             // 2560

__device__ __forceinline__ void cpa16(uint32_t dst, const __half* src) {
    asm volatile("cp.async.cg.shared.global [%0], [%1], 16;" :: "r"(dst), "l"(src));
}

__global__ __launch_bounds__(256) void gemm_f16_kernel(
        float* __restrict__ Yq, __half* __restrict__ Ykh, __half* __restrict__ Yvh,
        const __half* __restrict__ A,
        const __half* __restrict__ W0, const __half* __restrict__ W1, const __half* __restrict__ W2,
        const float* __restrict__ b0p, const float* __restrict__ b1p, const float* __restrict__ b2p) {
    const int M_K = 256;
    __shared__ __align__(16) __half smA[2][A_HALF];
    __shared__ __align__(16) __half smB[2][B_HALF];

    int z = blockIdx.z;
    const __half* W = (z == 0) ? W0 : (z == 1) ? W1 : W2;
    const float* bias = (z == 0) ? b0p : (z == 1) ? b1p : b2p;

    int tid = threadIdx.x;
    int lane = tid & 31;
    int warp = tid >> 5;
    int wm = warp & 3;
    int wn = warp >> 2;
    int mBase = blockIdx.y * 128;
    int nBase = blockIdx.x * 64;

    float c[8][4];
#pragma unroll
    for (int i = 0; i < 8; i++)
#pragma unroll
        for (int j = 0; j < 4; j++) c[i][j] = 0.f;

    // ldmatrix lane mappings (b16 tiles)
    int a_row = lane & 15;
    int a_colh = (lane >> 4) * 8;                  // 0 or 8 halves
    int b_row = (lane & 7) | ((lane >> 1) & 8);    // n-row within 16
    int b_colh = ((lane >> 3) & 1) * 8;            // 0 or 8 halves

    uint32_t as_base = (uint32_t)__cvta_generic_to_shared(&smA[0][0]);
    uint32_t bs_base = (uint32_t)__cvta_generic_to_shared(&smB[0][0]);
    uint32_t a_addr0 = as_base + ((wm * 32 + a_row) * SMH + a_colh) * 2u;
    uint32_t a_addr1 = a_addr0 + 16u * SMH * 2u;
    uint32_t b_addr0 = bs_base + ((wn * 32 + b_row) * SMH + b_colh) * 2u;
    uint32_t b_addr1 = b_addr0 + 16u * SMH * 2u;

    // cp.async layout: thread t copies 16B segs; row = t>>2 (0..63), seg = t&3
    int ld_row = tid >> 2;
    int ld_segh = (tid & 3) * 8;                   // halves

    const __half* aSrc = A + (size_t)(mBase + ld_row) * M_K + ld_segh;
    const __half* bSrc = W + (size_t)(nBase + ld_row) * M_K + ld_segh;
    uint32_t aDst = as_base + (uint32_t)(ld_row * SMH + ld_segh) * 2u;
    uint32_t bDst = bs_base + (uint32_t)(ld_row * SMH + ld_segh) * 2u;

#define ISSUE_CHUNK(KT)                                                         \
    do {                                                                        \
        int _buf = (KT) & 1;                                                    \
        uint32_t _ao = (uint32_t)_buf * (A_HALF * 2u);                          \
        uint32_t _bo = (uint32_t)_buf * (B_HALF * 2u);                          \
        int _ko = (KT) * 32;                                                    \
        cpa16(aDst + _ao,                     aSrc + _ko);                      \
        cpa16(aDst + _ao + 64u * SMH * 2u,    aSrc + (size_t)64 * M_K + _ko);   \
        cpa16(bDst + _bo,                     bSrc + _ko);                      \
        asm volatile("cp.async.commit_group;" ::: "memory");                    \
    } while (0)

    ISSUE_CHUNK(0);

    for (int kt = 0; kt < 8; kt++) {
        asm volatile("cp.async.wait_group 0;" ::: "memory");
        __syncthreads();
        if (kt < 7) ISSUE_CHUNK(kt + 1);

        int buf = kt & 1;
        uint32_t aBufOff = (uint32_t)buf * (A_HALF * 2u);
        uint32_t bBufOff = (uint32_t)buf * (B_HALF * 2u);
#pragma unroll
        for (int ks = 0; ks < 2; ks++) {
            uint32_t kb = (uint32_t)(ks * 16) * 2u;    // 16 halves per k16 step
            uint32_t a0, a1, a2, a3, a4, a5, a6, a7;
            asm volatile(
                "ldmatrix.sync.aligned.m8n8.x4.shared.b16 {%0,%1,%2,%3}, [%4];"
                : "=r"(a0), "=r"(a1), "=r"(a2), "=r"(a3)
                : "r"(a_addr0 + aBufOff + kb));
            asm volatile(
                "ldmatrix.sync.aligned.m8n8.x4.shared.b16 {%0,%1,%2,%3}, [%4];"
                : "=r"(a4), "=r"(a5), "=r"(a6), "=r"(a7)
                : "r"(a_addr1 + aBufOff + kb));
            uint32_t bb0, bb1, bb2, bb3, bb4, bb5, bb6, bb7;
            asm volatile(
                "ldmatrix.sync.aligned.m8n8.x4.shared.b16 {%0,%1,%2,%3}, [%4];"
                : "=r"(bb0), "=r"(bb1), "=r"(bb2), "=r"(bb3)
                : "r"(b_addr0 + bBufOff + kb));
            asm volatile(
                "ldmatrix.sync.aligned.m8n8.x4.shared.b16 {%0,%1,%2,%3}, [%4];"
                : "=r"(bb4), "=r"(bb5), "=r"(bb6), "=r"(bb7)
                : "r"(b_addr1 + bBufOff + kb));

#define MMAH(CI, AA0, AA1, AA2, AA3, B0, B1)                               \
            asm volatile(                                                  \
                "mma.sync.aligned.m16n8k16.row.col.f32.f16.f16.f32 "       \
                "{%0,%1,%2,%3}, {%4,%5,%6,%7}, {%8,%9}, {%0,%1,%2,%3};"    \
                : "+f"(c[CI][0]), "+f"(c[CI][1]), "+f"(c[CI][2]), "+f"(c[CI][3]) \
                : "r"(AA0), "r"(AA1), "r"(AA2), "r"(AA3), "r"(B0), "r"(B1))
            MMAH(0, a0, a1, a2, a3, bb0, bb1);
            MMAH(1, a0, a1, a2, a3, bb2, bb3);
            MMAH(2, a0, a1, a2, a3, bb4, bb5);
            MMAH(3, a0, a1, a2, a3, bb6, bb7);
            MMAH(4, a4, a5, a6, a7, bb0, bb1);
            MMAH(5, a4, a5, a6, a7, bb2, bb3);
            MMAH(6, a4, a5, a6, a7, bb4, bb5);
            MMAH(7, a4, a5, a6, a7, bb6, bb7);
#undef MMAH
        }
    }
#undef ISSUE_CHUNK

    // epilogue: z==0 -> fp32 (Yq); z==1 -> fp16 K; z==2 -> fp16 V
    int rowB = mBase + wm * 32 + (lane >> 2);
    __half* Yh = (z == 1) ? Ykh : Yvh;
#pragma unroll
    for (int mt = 0; mt < 2; mt++) {
#pragma unroll
        for (int g = 0; g < 4; g++) {
            int ci = mt * 4 + g;
            int row = rowB + mt * 16;
            int col = nBase + wn * 32 + g * 8 + (lane & 3) * 2;
            float b0 = bias[col], b1 = bias[col + 1];
            float r00 = c[ci][0] + b0, r01 = c[ci][1] + b1;
            float r10 = c[ci][2] + b0, r11 = c[ci][3] + b1;
            if (z == 0) {
                *(float2*)&Yq[(size_t)row * M_K + col] = make_float2(r00, r01);
                *(float2*)&Yq[(size_t)(row + 8) * M_K + col] = make_float2(r10, r11);
            } else {
                *(__half2*)&Yh[(size_t)row * M_K + col] = __floats2half2_rn(r00, r01);
                *(__half2*)&Yh[(size_t)(row + 8) * M_K + col] = __floats2half2_rn(r10, r11);
            }
        }
    }
}

// ---------------- sparse masked attention: warp w = head w (K,V fp16) ---------
__global__ __launch_bounds__(128) void attn_kernel(
        __half* __restrict__ out,
        const float* __restrict__ q,
        const __half* __restrict__ kh,
        const __half* __restrict__ vh) {
    __shared__ unsigned short nbr[CAP];
    __shared__ float sc[HEADS][CAP];
    __shared__ int warpSum[4];
    __shared__ int warpBase[4];
    __shared__ int deg_s;

    int i = blockIdx.x;
    int tid = threadIdx.x;          // 128 threads
    int lane = tid & 31;
    int wid = tid >> 5;             // head index

    // ---- deterministic neighbor gather ----
    uint2 wpair = *(const uint2*)&g_bitmap[i * WORDS_PER_ROW + tid * 2];
    unsigned w0 = wpair.x, w1 = wpair.y;
    int c = __popc(w0) + __popc(w1);
    int incl = c;
#pragma unroll
    for (int d = 1; d < 32; d <<= 1) {
        int n_ = __shfl_up_sync(0xffffffffu, incl, d);
        if (lane >= d) incl += n_;
    }
    if (lane == 31) warpSum[wid] = incl;
    __syncthreads();
    if (tid < 4) {
        int e = 0;
        for (int j2 = 0; j2 < tid; j2++) e += warpSum[j2];
        warpBase[tid] = e;
        if (tid == 3) deg_s = e + warpSum[3];
    }
    __syncthreads();
    int off = warpBase[wid] + (incl - c);
    int base0 = tid * 64;
    while (w0) {
        int b = __ffs(w0) - 1;
        w0 &= w0 - 1;
        if (off < CAP) nbr[off] = (unsigned short)(base0 + b);
        off++;
    }
    while (w1) {
        int b = __ffs(w1) - 1;
        w1 &= w1 - 1;
        if (off < CAP) nbr[off] = (unsigned short)(base0 + 32 + b);
        off++;
    }
    __syncthreads();
    int deg = min(deg_s, CAP);

    // ---- scores: 4 neighbors/warp-iter; 8-lane groups; one uint4 K load ----
    {
        int sub = lane >> 3;
        int chBase = (lane & 7) * 8;
        const float* qRow = q + (size_t)i * H_CH + wid * HEAD_DIM + chBase;
        float4 q0 = *(const float4*)qRow;
        float4 q1 = *(const float4*)(qRow + 4);
        for (int j = 0; j < deg; j += 4) {
            int jj = j + sub;
            bool valid = (jj < deg);
            int n = nbr[valid ? jj : 0];
            uint4 raw = *(const uint4*)(kh + (size_t)n * H_CH + wid * HEAD_DIM + chBase);
            float2 f0 = __half22float2(*(__half2*)&raw.x);
            float2 f1 = __half22float2(*(__half2*)&raw.y);
            float2 f2 = __half22float2(*(__half2*)&raw.z);
            float2 f3 = __half22float2(*(__half2*)&raw.w);
            float p = f0.x * q0.x + f0.y * q0.y + f1.x * q0.z + f1.y * q0.w
                    + f2.x * q1.x + f2.y * q1.y + f3.x * q1.z + f3.y * q1.w;
            p += __shfl_xor_sync(0xffffffffu, p, 1);
            p += __shfl_xor_sync(0xffffffffu, p, 2);
            p += __shfl_xor_sync(0xffffffffu, p, 4);
            if (valid && (lane & 7) == 0) sc[wid][jj] = p * 0.125f;
        }
    }
    __syncwarp();

    // ---- warp-local softmax ----
    float m = -1e30f;
    for (int t = lane; t < deg; t += 32) m = fmaxf(m, sc[wid][t]);
#pragma unroll
    for (int d = 16; d; d >>= 1) m = fmaxf(m, __shfl_xor_sync(0xffffffffu, m, d));
    float l = 0.f;
    for (int t = lane; t < deg; t += 32) {
        float p = __expf(sc[wid][t] - m);
        sc[wid][t] = p;
        l += p;
    }
#pragma unroll
    for (int d = 16; d; d >>= 1) l += __shfl_xor_sync(0xffffffffu, l, d);
    float linv = 1.0f / l;
    __syncwarp();

    // ---- weighted V (fp16): 2 neighbors/warp-iter; fp16 output ----
    {
        int half = lane >> 4;
        int chBase = (lane & 15) * 4;
        size_t vOff = (size_t)wid * HEAD_DIM + chBase;
        float4 acc = make_float4(0.f, 0.f, 0.f, 0.f);
        for (int t = 0; t < deg; t += 2) {
            int tt = t + half;
            bool valid = (tt < deg);
            int n = nbr[valid ? tt : 0];
            float s = valid ? sc[wid][tt] : 0.f;
            uint2 raw = *(const uint2*)(vh + (size_t)n * H_CH + vOff);
            float2 f0 = __half22float2(*(__half2*)&raw.x);
            float2 f1 = __half22float2(*(__half2*)&raw.y);
            acc.x += s * f0.x; acc.y += s * f0.y;
            acc.z += s * f1.x; acc.w += s * f1.y;
        }
        acc.x += __shfl_xor_sync(0xffffffffu, acc.x, 16);
        acc.y += __shfl_xor_sync(0xffffffffu, acc.y, 16);
        acc.z += __shfl_xor_sync(0xffffffffu, acc.z, 16);
        acc.w += __shfl_xor_sync(0xffffffffu, acc.w, 16);
        if (half == 0) {
            __half2 o0 = __floats2half2_rn(acc.x * linv, acc.y * linv);
            __half2 o1 = __floats2half2_rn(acc.z * linv, acc.w * linv);
            uint2 packed;
            packed.x = *(uint32_t*)&o0;
            packed.y = *(uint32_t*)&o1;
            *(uint2*)(out + (size_t)i * H_CH + vOff) = packed;
        }
    }
}

// ---------------- launch ----------------
extern "C" void kernel_launch(void* const* d_in, const int* in_sizes, int n_in,
                              void* d_out, int out_size) {
    const float* x  = (const float*)d_in[0];
    const void*  ei = d_in[1];
    const float* Wq = (const float*)d_in[2];
    const float* bq = (const float*)d_in[3];
    const float* Wk = (const float*)d_in[4];
    const float* bk = (const float*)d_in[5];
    const float* Wv = (const float*)d_in[6];
    const float* bv = (const float*)d_in[7];
    const float* Wo = (const float*)d_in[8];
    const float* bo = (const float*)d_in[9];
    float* out = (float*)d_out;

    float *qp;
    __half *xhp, *whp, *khp, *vhp, *ahp;
    cudaGetSymbolAddress((void**)&xhp, g_xh);
    cudaGetSymbolAddress((void**)&whp, g_wh);
    cudaGetSymbolAddress((void**)&qp, g_q);
    cudaGetSymbolAddress((void**)&khp, g_kh);
    cudaGetSymbolAddress((void**)&vhp, g_vh);
    cudaGetSymbolAddress((void**)&ahp, g_ah);

    detect_dtype_kernel<<<1, 128>>>((const unsigned*)ei);
    zero_bitmap_kernel<<<512, 256>>>();
    scatter_edges_kernel<<<(E_EDGES + 255) / 256, 256>>>(ei);

    // merged fp16 conversion: x + 4 weights, 2 float4 per thread
    cvt_all_f16_kernel<<<(TOT_F4 / 2 + 255) / 256, 256>>>(x, Wq, Wk, Wv, Wo);

    // fused QKV: z=0 Q (fp32), z=1 K (fp16), z=2 V (fp16)
    dim3 qkv_grid(H_CH / 64, N_NODES / 128, 3);
    gemm_f16_kernel<<<qkv_grid, 256>>>(
        qp, khp, vhp, xhp,
        whp + 0 * H_CH * H_CH, whp + 1 * H_CH * H_CH, whp + 2 * H_CH * H_CH,
        bq, bk, bv);

    attn_kernel<<<N_NODES, 128>>>(ahp, qp, khp, vhp);

    // O-GEMM: z=0, fp32 out; A = attn output (fp16)
    dim3 o_grid(H_CH / 64, N_NODES / 128, 1);
    gemm_f16_kernel<<<o_grid, 256>>>(
        out, khp, vhp, ahp,
        whp + 3 * H_CH * H_CH, whp + 3 * H_CH * H_CH, whp + 3 * H_CH * H_CH,
        bo, bo, bo);
}

// round 14
// speedup vs baseline: 4.8889x; 1.0278x over previous
#include <cuda_runtime.h>
#include <cuda_fp16.h>
#include <stdint.h>
#include <math.h>

#define N_NODES 8192
#define H_CH 256
#define HEADS 4
#define HEAD_DIM 64
#define E_EDGES 262144
#define WORDS_PER_ROW (N_NODES / 32)   // 256
#define CAP 256

// ---------------- device scratch ----------------
__device__ __align__(128) __half  g_xh[N_NODES * H_CH];    // x in fp16
__device__ __align__(128) __half  g_wh[4][H_CH * H_CH];    // Wq,Wk,Wv,Wo fp16
__device__ __align__(128) __half  g_qh[N_NODES * H_CH];
__device__ __align__(128) __half  g_kh[N_NODES * H_CH];
__device__ __align__(128) __half  g_vh[N_NODES * H_CH];
__device__ __align__(128) __half  g_ah[N_NODES * H_CH];    // attn output fp16
__device__ __align__(16) unsigned g_bitmap[N_NODES * WORDS_PER_ROW];
__device__ int      g_is64;

// ---------------- edge dtype detection (parallel) ----------------
__global__ void detect_dtype_kernel(const unsigned* __restrict__ ei_words) {
    __shared__ int bad[4];
    int tid = threadIdx.x;                 // 128 threads
    unsigned v = ei_words[2 * tid + 1];
    unsigned b = __ballot_sync(0xffffffffu, v != 0u);
    if ((tid & 31) == 0) bad[tid >> 5] = (b != 0u);
    __syncthreads();
    if (tid == 0) g_is64 = !(bad[0] | bad[1] | bad[2] | bad[3]);
}

// ---------------- prep: zero bitmap + fp32->fp16 cvt of x and weights --------
#define BM_U4  (N_NODES * WORDS_PER_ROW / 4)   // 524288 uint4 zeros
#define X_F4   (N_NODES * H_CH / 4)            // 524288 float4s
#define W_F4   (H_CH * H_CH / 4)               // 16384 float4s per W
#define CVT_F4 (X_F4 + 4 * W_F4)               // 589824
#define PREP_TOT (BM_U4 + CVT_F4)

__global__ void prep_kernel(const float* __restrict__ x,
                            const float* __restrict__ w0,
                            const float* __restrict__ w1,
                            const float* __restrict__ w2,
                            const float* __restrict__ w3) {
    for (int i = blockIdx.x * blockDim.x + threadIdx.x; i < PREP_TOT;
         i += gridDim.x * blockDim.x) {
        if (i < BM_U4) {
            ((uint4*)g_bitmap)[i] = make_uint4(0u, 0u, 0u, 0u);
        } else {
            int j = i - BM_U4;
            const float* src;
            __half* dst;
            int idx;
            if (j < X_F4) {
                src = x; dst = g_xh; idx = j;
            } else {
                int j2 = j - X_F4;
                int z = j2 >> 14;
                idx = j2 & 16383;
                src = (z == 0) ? w0 : (z == 1) ? w1 : (z == 2) ? w2 : w3;
                dst = g_wh[z];
            }
            float4 f = ((const float4*)src)[idx];
            __half2 lo = __floats2half2_rn(f.x, f.y);
            __half2 hi = __floats2half2_rn(f.z, f.w);
            uint2 packed;
            packed.x = *(uint32_t*)&lo;
            packed.y = *(uint32_t*)&hi;
            ((uint2*)dst)[idx] = packed;
        }
    }
}

// ---------------- edge scatter ----------------
__global__ void scatter_edges_kernel(const void* __restrict__ ei_raw) {
    int e = blockIdx.x * blockDim.x + threadIdx.x;
    if (e >= E_EDGES) return;
    int r, c;
    if (g_is64) {
        const long long* ei = (const long long*)ei_raw;
        r = (int)ei[e];
        c = (int)ei[E_EDGES + e];
    } else {
        const int* ei = (const int*)ei_raw;
        r = ei[e];
        c = ei[E_EDGES + e];
    }
    if ((unsigned)r < N_NODES && (unsigned)c < N_NODES)
        atomicOr(&g_bitmap[r * WORDS_PER_ROW + (c >> 5)], 1u << (c & 31));
}

// ---------------- fp16 tensor GEMM: 3-stage cp.async pipeline -----------------
// m16n8k16 fp16 mma, fp32 accum; 128x64 block tile; 32-k chunks.
#define SMH 40                        // half-stride per row (80B)
#define A_HALF (128 * SMH)            // 5120
#define B_HALF (64 * SMH)             // 2560

__device__ __forceinline__ void cpa16(uint32_t dst, const __half* src) {
    asm volatile("cp.async.cg.shared.global [%0], [%1], 16;" :: "r"(dst), "l"(src));
}

__global__ __launch_bounds__(256) void gemm_f16_kernel(
        __half* __restrict__ Y0h, __half* __restrict__ Y1h, __half* __restrict__ Y2h,
        float* __restrict__ Yf, int fp32_out,
        const __half* __restrict__ A,
        const __half* __restrict__ W0, const __half* __restrict__ W1, const __half* __restrict__ W2,
        const float* __restrict__ b0p, const float* __restrict__ b1p, const float* __restrict__ b2p) {
    const int M_K = 256;
    __shared__ __align__(16) __half smA[3][A_HALF];
    __shared__ __align__(16) __half smB[3][B_HALF];

    int z = blockIdx.z;
    const __half* W = (z == 0) ? W0 : (z == 1) ? W1 : W2;
    const float* bias = (z == 0) ? b0p : (z == 1) ? b1p : b2p;

    int tid = threadIdx.x;
    int lane = tid & 31;
    int warp = tid >> 5;
    int wm = warp & 3;
    int wn = warp >> 2;
    int mBase = blockIdx.y * 128;
    int nBase = blockIdx.x * 64;

    float c[8][4];
#pragma unroll
    for (int i = 0; i < 8; i++)
#pragma unroll
        for (int j = 0; j < 4; j++) c[i][j] = 0.f;

    int a_row = lane & 15;
    int a_colh = (lane >> 4) * 8;
    int b_row = (lane & 7) | ((lane >> 1) & 8);
    int b_colh = ((lane >> 3) & 1) * 8;

    uint32_t as_base = (uint32_t)__cvta_generic_to_shared(&smA[0][0]);
    uint32_t bs_base = (uint32_t)__cvta_generic_to_shared(&smB[0][0]);
    uint32_t a_addr0 = as_base + ((wm * 32 + a_row) * SMH + a_colh) * 2u;
    uint32_t a_addr1 = a_addr0 + 16u * SMH * 2u;
    uint32_t b_addr0 = bs_base + ((wn * 32 + b_row) * SMH + b_colh) * 2u;
    uint32_t b_addr1 = b_addr0 + 16u * SMH * 2u;

    int ld_row = tid >> 2;
    int ld_segh = (tid & 3) * 8;

    const __half* aSrc = A + (size_t)(mBase + ld_row) * M_K + ld_segh;
    const __half* bSrc = W + (size_t)(nBase + ld_row) * M_K + ld_segh;
    uint32_t aDst = as_base + (uint32_t)(ld_row * SMH + ld_segh) * 2u;
    uint32_t bDst = bs_base + (uint32_t)(ld_row * SMH + ld_segh) * 2u;

#define ISSUE_CHUNK(KT)                                                         \
    do {                                                                        \
        int _buf = (KT) % 3;                                                    \
        uint32_t _ao = (uint32_t)_buf * (A_HALF * 2u);                          \
        uint32_t _bo = (uint32_t)_buf * (B_HALF * 2u);                          \
        int _ko = (KT) * 32;                                                    \
        cpa16(aDst + _ao,                  aSrc + _ko);                         \
        cpa16(aDst + _ao + 64u * SMH * 2u, aSrc + (size_t)64 * M_K + _ko);      \
        cpa16(bDst + _bo,                  bSrc + _ko);                         \
        asm volatile("cp.async.commit_group;" ::: "memory");                    \
    } while (0)

    ISSUE_CHUNK(0);
    ISSUE_CHUNK(1);

    for (int kt = 0; kt < 8; kt++) {
        if (kt < 7)
            asm volatile("cp.async.wait_group 1;" ::: "memory");
        else
            asm volatile("cp.async.wait_group 0;" ::: "memory");
        __syncthreads();
        if (kt < 6) ISSUE_CHUNK(kt + 2);

        int buf = kt % 3;
        uint32_t aBufOff = (uint32_t)buf * (A_HALF * 2u);
        uint32_t bBufOff = (uint32_t)buf * (B_HALF * 2u);
#pragma unroll
        for (int ks = 0; ks < 2; ks++) {
            uint32_t kb = (uint32_t)(ks * 16) * 2u;
            uint32_t a0, a1, a2, a3, a4, a5, a6, a7;
            asm volatile(
                "ldmatrix.sync.aligned.m8n8.x4.shared.b16 {%0,%1,%2,%3}, [%4];"
                : "=r"(a0), "=r"(a1), "=r"(a2), "=r"(a3)
                : "r"(a_addr0 + aBufOff + kb));
            asm volatile(
                "ldmatrix.sync.aligned.m8n8.x4.shared.b16 {%0,%1,%2,%3}, [%4];"
                : "=r"(a4), "=r"(a5), "=r"(a6), "=r"(a7)
                : "r"(a_addr1 + aBufOff + kb));
            uint32_t bb0, bb1, bb2, bb3, bb4, bb5, bb6, bb7;
            asm volatile(
                "ldmatrix.sync.aligned.m8n8.x4.shared.b16 {%0,%1,%2,%3}, [%4];"
                : "=r"(bb0), "=r"(bb1), "=r"(bb2), "=r"(bb3)
                : "r"(b_addr0 + bBufOff + kb));
            asm volatile(
                "ldmatrix.sync.aligned.m8n8.x4.shared.b16 {%0,%1,%2,%3}, [%4];"
                : "=r"(bb4), "=r"(bb5), "=r"(bb6), "=r"(bb7)
                : "r"(b_addr1 + bBufOff + kb));

#define MMAH(CI, AA0, AA1, AA2, AA3, B0, B1)                               \
            asm volatile(                                                  \
                "mma.sync.aligned.m16n8k16.row.col.f32.f16.f16.f32 "       \
                "{%0,%1,%2,%3}, {%4,%5,%6,%7}, {%8,%9}, {%0,%1,%2,%3};"    \
                : "+f"(c[CI][0]), "+f"(c[CI][1]), "+f"(c[CI][2]), "+f"(c[CI][3]) \
                : "r"(AA0), "r"(AA1), "r"(AA2), "r"(AA3), "r"(B0), "r"(B1))
            MMAH(0, a0, a1, a2, a3, bb0, bb1);
            MMAH(1, a0, a1, a2, a3, bb2, bb3);
            MMAH(2, a0, a1, a2, a3, bb4, bb5);
            MMAH(3, a0, a1, a2, a3, bb6, bb7);
            MMAH(4, a4, a5, a6, a7, bb0, bb1);
            MMAH(5, a4, a5, a6, a7, bb2, bb3);
            MMAH(6, a4, a5, a6, a7, bb4, bb5);
            MMAH(7, a4, a5, a6, a7, bb6, bb7);
#undef MMAH
        }
    }
#undef ISSUE_CHUNK

    // epilogue
    int rowB = mBase + wm * 32 + (lane >> 2);
    __half* Yh = (z == 0) ? Y0h : (z == 1) ? Y1h : Y2h;
#pragma unroll
    for (int mt = 0; mt < 2; mt++) {
#pragma unroll
        for (int g = 0; g < 4; g++) {
            int ci = mt * 4 + g;
            int row = rowB + mt * 16;
            int col = nBase + wn * 32 + g * 8 + (lane & 3) * 2;
            float b0 = bias[col], b1 = bias[col + 1];
            float r00 = c[ci][0] + b0, r01 = c[ci][1] + b1;
            float r10 = c[ci][2] + b0, r11 = c[ci][3] + b1;
            if (fp32_out) {
                *(float2*)&Yf[(size_t)row * M_K + col] = make_float2(r00, r01);
                *(float2*)&Yf[(size_t)(row + 8) * M_K + col] = make_float2(r10, r11);
            } else {
                *(__half2*)&Yh[(size_t)row * M_K + col] = __floats2half2_rn(r00, r01);
                *(__half2*)&Yh[(size_t)(row + 8) * M_K + col] = __floats2half2_rn(r10, r11);
            }
        }
    }
}

// ---------------- sparse masked attention: warp w = head w (all fp16) ---------
__global__ __launch_bounds__(128) void attn_kernel(
        __half* __restrict__ out,
        const __half* __restrict__ qh,
        const __half* __restrict__ kh,
        const __half* __restrict__ vh) {
    __shared__ unsigned short nbr[CAP];
    __shared__ float sc[HEADS][CAP];
    __shared__ int warpSum[4];
    __shared__ int warpBase[4];
    __shared__ int deg_s;

    int i = blockIdx.x;
    int tid = threadIdx.x;          // 128 threads
    int lane = tid & 31;
    int wid = tid >> 5;             // head index

    // ---- deterministic neighbor gather ----
    uint2 wpair = *(const uint2*)&g_bitmap[i * WORDS_PER_ROW + tid * 2];
    unsigned w0 = wpair.x, w1 = wpair.y;
    int c = __popc(w0) + __popc(w1);
    int incl = c;
#pragma unroll
    for (int d = 1; d < 32; d <<= 1) {
        int n_ = __shfl_up_sync(0xffffffffu, incl, d);
        if (lane >= d) incl += n_;
    }
    if (lane == 31) warpSum[wid] = incl;
    __syncthreads();
    if (tid < 4) {
        int e = 0;
        for (int j2 = 0; j2 < tid; j2++) e += warpSum[j2];
        warpBase[tid] = e;
        if (tid == 3) deg_s = e + warpSum[3];
    }
    __syncthreads();
    int off = warpBase[wid] + (incl - c);
    int base0 = tid * 64;
    while (w0) {
        int b = __ffs(w0) - 1;
        w0 &= w0 - 1;
        if (off < CAP) nbr[off] = (unsigned short)(base0 + b);
        off++;
    }
    while (w1) {
        int b = __ffs(w1) - 1;
        w1 &= w1 - 1;
        if (off < CAP) nbr[off] = (unsigned short)(base0 + 32 + b);
        off++;
    }
    __syncthreads();
    int deg = min(deg_s, CAP);

    // ---- scores: 4 neighbors/warp-iter; 8-lane groups; one uint4 K load ----
    {
        int sub = lane >> 3;
        int chBase = (lane & 7) * 8;
        uint4 qraw = *(const uint4*)(qh + (size_t)i * H_CH + wid * HEAD_DIM + chBase);
        float2 q0 = __half22float2(*(__half2*)&qraw.x);
        float2 q1 = __half22float2(*(__half2*)&qraw.y);
        float2 q2 = __half22float2(*(__half2*)&qraw.z);
        float2 q3 = __half22float2(*(__half2*)&qraw.w);
        for (int j = 0; j < deg; j += 4) {
            int jj = j + sub;
            bool valid = (jj < deg);
            int n = nbr[valid ? jj : 0];
            uint4 raw = *(const uint4*)(kh + (size_t)n * H_CH + wid * HEAD_DIM + chBase);
            float2 f0 = __half22float2(*(__half2*)&raw.x);
            float2 f1 = __half22float2(*(__half2*)&raw.y);
            float2 f2 = __half22float2(*(__half2*)&raw.z);
            float2 f3 = __half22float2(*(__half2*)&raw.w);
            float p = f0.x * q0.x + f0.y * q0.y + f1.x * q1.x + f1.y * q1.y
                    + f2.x * q2.x + f2.y * q2.y + f3.x * q3.x + f3.y * q3.y;
            p += __shfl_xor_sync(0xffffffffu, p, 1);
            p += __shfl_xor_sync(0xffffffffu, p, 2);
            p += __shfl_xor_sync(0xffffffffu, p, 4);
            if (valid && (lane & 7) == 0) sc[wid][jj] = p * 0.125f;
        }
    }
    __syncwarp();

    // ---- warp-local softmax ----
    float m = -1e30f;
    for (int t = lane; t < deg; t += 32) m = fmaxf(m, sc[wid][t]);
#pragma unroll
    for (int d = 16; d; d >>= 1) m = fmaxf(m, __shfl_xor_sync(0xffffffffu, m, d));
    float l = 0.f;
    for (int t = lane; t < deg; t += 32) {
        float p = __expf(sc[wid][t] - m);
        sc[wid][t] = p;
        l += p;
    }
#pragma unroll
    for (int d = 16; d; d >>= 1) l += __shfl_xor_sync(0xffffffffu, l, d);
    float linv = 1.0f / l;
    __syncwarp();

    // ---- weighted V (fp16): 2 neighbors/warp-iter; fp16 output ----
    {
        int half = lane >> 4;
        int chBase = (lane & 15) * 4;
        size_t vOff = (size_t)wid * HEAD_DIM + chBase;
        float4 acc = make_float4(0.f, 0.f, 0.f, 0.f);
        for (int t = 0; t < deg; t += 2) {
            int tt = t + half;
            bool valid = (tt < deg);
            int n = nbr[valid ? tt : 0];
            float s = valid ? sc[wid][tt] : 0.f;
            uint2 raw = *(const uint2*)(vh + (size_t)n * H_CH + vOff);
            float2 f0 = __half22float2(*(__half2*)&raw.x);
            float2 f1 = __half22float2(*(__half2*)&raw.y);
            acc.x += s * f0.x; acc.y += s * f0.y;
            acc.z += s * f1.x; acc.w += s * f1.y;
        }
        acc.x += __shfl_xor_sync(0xffffffffu, acc.x, 16);
        acc.y += __shfl_xor_sync(0xffffffffu, acc.y, 16);
        acc.z += __shfl_xor_sync(0xffffffffu, acc.z, 16);
        acc.w += __shfl_xor_sync(0xffffffffu, acc.w, 16);
        if (half == 0) {
            __half2 o0 = __floats2half2_rn(acc.x * linv, acc.y * linv);
            __half2 o1 = __floats2half2_rn(acc.z * linv, acc.w * linv);
            uint2 packed;
            packed.x = *(uint32_t*)&o0;
            packed.y = *(uint32_t*)&o1;
            *(uint2*)(out + (size_t)i * H_CH + vOff) = packed;
        }
    }
}

// ---------------- launch ----------------
extern "C" void kernel_launch(void* const* d_in, const int* in_sizes, int n_in,
                              void* d_out, int out_size) {
    const float* x  = (const float*)d_in[0];
    const void*  ei = d_in[1];
    const float* Wq = (const float*)d_in[2];
    const float* bq = (const float*)d_in[3];
    const float* Wk = (const float*)d_in[4];
    const float* bk = (const float*)d_in[5];
    const float* Wv = (const float*)d_in[6];
    const float* bv = (const float*)d_in[7];
    const float* Wo = (const float*)d_in[8];
    const float* bo = (const float*)d_in[9];
    float* out = (float*)d_out;

    __half *whp, *qhp, *khp, *vhp, *ahp, *xhp;
    cudaGetSymbolAddress((void**)&xhp, g_xh);
    cudaGetSymbolAddress((void**)&whp, g_wh);
    cudaGetSymbolAddress((void**)&qhp, g_qh);
    cudaGetSymbolAddress((void**)&khp, g_kh);
    cudaGetSymbolAddress((void**)&vhp, g_vh);
    cudaGetSymbolAddress((void**)&ahp, g_ah);

    detect_dtype_kernel<<<1, 128>>>((const unsigned*)ei);
    prep_kernel<<<2048, 256>>>(x, Wq, Wk, Wv, Wo);
    scatter_edges_kernel<<<(E_EDGES + 255) / 256, 256>>>(ei);

    // fused QKV: all outputs fp16
    dim3 qkv_grid(H_CH / 64, N_NODES / 128, 3);
    gemm_f16_kernel<<<qkv_grid, 256>>>(
        qhp, khp, vhp, nullptr, 0, xhp,
        whp + 0 * H_CH * H_CH, whp + 1 * H_CH * H_CH, whp + 2 * H_CH * H_CH,
        bq, bk, bv);

    attn_kernel<<<N_NODES, 128>>>(ahp, qhp, khp, vhp);

    // O-GEMM: fp32 out
    dim3 o_grid(H_CH / 64, N_NODES / 128, 1);
    gemm_f16_kernel<<<o_grid, 256>>>(
        ahp, ahp, ahp, out, 1, ahp,
        whp + 3 * H_CH * H_CH, whp + 3 * H_CH * H_CH, whp + 3 * H_CH * H_CH,
        bo, bo, bo);
}